// round 5
// baseline (speedup 1.0000x reference)
#include <cuda_runtime.h>
#include <cuda_bf16.h>

// ---------------------------------------------------------------------------
// Tagger: 2-layer bidirectional LSTM (B=S=512, E=20, H1=30, H2=50, NTAGS=45)
// Reference quirk: (S,B,H)->(B,S,H) reshape with S==B is an index swap.
// Storage convention (all [time][batch][h]):
//   F1[t][b], B1[t][b]  : layer-1 hidden at time t, batch b
//   layer-2 row rho consumes at step u: ( F1[rho][u], B1[511-rho][u] )
//   F2 stored [u][rho]; B2 stored [511-u][rho]  =>  OUT reads both at [i][j].
// Gate math uses packed fp32 pairs via fma.rn.f32x2 (FFMA2) with LDS.128
// operands. Gate dot products are SPLIT across threads: x-part (Wih·x) and
// h-part (Whh·h) run in different warps, doubling warps/SM for latency hiding.
// ---------------------------------------------------------------------------

typedef unsigned long long u64;

__device__ float g_F1[512 * 512 * 30];
__device__ float g_B1[512 * 512 * 30];
__device__ float g_F2[512 * 512 * 50];
__device__ float g_B2[512 * 512 * 50];
__device__ int   g_xidx[512 * 512];
__device__ int   g_is64;

__device__ __forceinline__ void fma2(u64 &acc, u64 a, u64 b) {
    asm("fma.rn.f32x2 %0, %1, %2, %0;" : "+l"(acc) : "l"(a), "l"(b));
}
__device__ __forceinline__ float2 up2(u64 v) {
    float2 r; asm("mov.b64 {%0, %1}, %2;" : "=f"(r.x), "=f"(r.y) : "l"(v));
    return r;
}

__device__ __forceinline__ float sigm(float x) {
    return __fdividef(1.f, 1.f + __expf(-x));
}
__device__ __forceinline__ float tanh_f(float x) {
    float a = fabsf(x);
    float e = __expf(-2.f * a);
    float t = __fdividef(1.f - e, 1.f + e);
    return x < 0.f ? -t : t;
}

// x may arrive as int32 (JAX default) or int64 (reference dtype). If int64,
// all odd 32-bit words are zero (tokens < 50000).
__global__ void detect_kernel(const int* __restrict__ xr) {
    int z = 0;
    for (int i = 1; i < 256; i += 2) z |= xr[i];
    g_is64 = (z == 0) ? 1 : 0;
}

__global__ void convert_kernel(const int* __restrict__ xr) {
    int i = blockIdx.x * blockDim.x + threadIdx.x;
    int is64 = g_is64;
    if (i < 512 * 512) g_xidx[i] = is64 ? xr[2 * i] : xr[i];
}

// ---------------------------------------------------------------------------
// Layer 1: 128 blocks (2 dirs x 64), 8 batch rows/block, 256 threads.
//   tid [0,120)    : x-part gate j = tid      (Wih row, 10 u64 regs)
//   tid [128,248)  : h-part gate j = tid-128  (Whh row, 15 u64 regs, + bias)
//   combine: 240 tasks on tid < 240
// ---------------------------------------------------------------------------
__global__ void __launch_bounds__(256, 1) r1_kernel(
    const float* __restrict__ emb_f, const float* __restrict__ emb_b,
    const float* __restrict__ h0f, const float* __restrict__ c0f,
    const float* __restrict__ Wihf, const float* __restrict__ Whhf,
    const float* __restrict__ bihf, const float* __restrict__ bhhf,
    const float* __restrict__ h0b, const float* __restrict__ c0b,
    const float* __restrict__ Wihb, const float* __restrict__ Whhb,
    const float* __restrict__ bihb, const float* __restrict__ bhhb)
{
    const int dir = blockIdx.x >> 6;           // 0 = forward, 1 = backward
    const int rowBase = (blockIdx.x & 63) * 8;
    const float* emb = dir ? emb_b : emb_f;
    const float* Wih = dir ? Wihb : Wihf;
    const float* Whh = dir ? Whhb : Whhf;
    const float* bih = dir ? bihb : bihf;
    const float* bhh = dir ? bhhb : bhhf;
    const float* h0  = dir ? h0b  : h0f;
    const float* c0  = dir ? c0b  : c0f;
    float* outp = dir ? g_B1 : g_F1;

    const int tid = threadIdx.x;
    __shared__ __align__(16) float h_sh[2][8][32];
    __shared__ __align__(16) float x_sh[2][8][20];
    __shared__ float xg_sh[8][120];
    __shared__ float hg_sh[8][120];

    const bool isX = (tid < 120);
    const bool isH = (tid >= 128 && tid < 248);
    const int  jg  = isX ? tid : (tid - 128);

    u64 wih2[10], whh2[15];
    float bias = 0.f;
    if (isX) {
        const u64* wa = (const u64*)(Wih + jg * 20);    // 80B rows, 8B-aligned
#pragma unroll
        for (int k = 0; k < 10; k++) wih2[k] = wa[k];
    }
    if (isH) {
        const u64* wb = (const u64*)(Whh + jg * 30);    // 120B rows, 8B-aligned
#pragma unroll
        for (int k = 0; k < 15; k++) whh2[k] = wb[k];
        bias = bih[jg] + bhh[jg];
    }
    for (int idx = tid; idx < 8 * 32; idx += 256) {
        int r = idx >> 5, k = idx & 31;
        h_sh[0][r][k] = (k < 30) ? h0[(rowBase + r) * 30 + k] : 0.f;
        h_sh[1][r][k] = 0.f;
    }
    // combine: task m = tid in [0,240): r = m/30, j = m%30
    const int r0 = tid / 30, j0 = tid - r0 * 30;
    const bool isC = (tid < 240);
    float cc0 = isC ? c0[(rowBase + r0) * 30 + j0] : 0.f;

    {   // preload x for step 0
        int t0 = dir ? 511 : 0;
        if (tid < 160) {
            int r = tid / 20, k = tid - r * 20;
            int tok = g_xidx[(rowBase + r) * 512 + t0];
            x_sh[0][r][k] = emb[tok * 20 + k];
        }
    }
    __syncthreads();

    int cur = 0;
    for (int s = 0; s < 512; s++) {
        const int t = dir ? (511 - s) : s;
        // issue next-step embedding loads early (hidden under FMA stretch)
        float pf0 = 0.f;
        if (s < 511 && tid < 160) {
            int tn = dir ? (510 - s) : (s + 1);
            int r = tid / 20, k = tid - r * 20;
            int tok = g_xidx[(rowBase + r) * 512 + tn];
            pf0 = emb[tok * 20 + k];
        }
        if (isX) {
#pragma unroll 2
            for (int r = 0; r < 8; r++) {
                const ulonglong2* xs = (const ulonglong2*)x_sh[cur][r];
                u64 ac0 = 0, ac1 = 0, ac2 = 0, ac3 = 0;
#pragma unroll
                for (int q = 0; q < 5; q++) {
                    ulonglong2 v = xs[q];
                    if (q & 1) { fma2(ac2, v.x, wih2[2 * q]); fma2(ac3, v.y, wih2[2 * q + 1]); }
                    else        { fma2(ac0, v.x, wih2[2 * q]); fma2(ac1, v.y, wih2[2 * q + 1]); }
                }
                float2 f0 = up2(ac0), f1 = up2(ac1), f2 = up2(ac2), f3 = up2(ac3);
                xg_sh[r][jg] = ((f0.x + f0.y) + (f1.x + f1.y))
                             + ((f2.x + f2.y) + (f3.x + f3.y));
            }
        } else if (isH) {
#pragma unroll 2
            for (int r = 0; r < 8; r++) {
                const ulonglong2* hs = (const ulonglong2*)h_sh[cur][r];
                u64 ac0 = 0, ac1 = 0, ac2 = 0, ac3 = 0;
#pragma unroll
                for (int q = 0; q < 7; q++) {
                    ulonglong2 v = hs[q];
                    if (q & 1) { fma2(ac2, v.x, whh2[2 * q]); fma2(ac3, v.y, whh2[2 * q + 1]); }
                    else        { fma2(ac0, v.x, whh2[2 * q]); fma2(ac1, v.y, whh2[2 * q + 1]); }
                }
                {
                    u64 tpair = *(const u64*)&h_sh[cur][r][28];
                    fma2(ac2, tpair, whh2[14]);
                }
                float2 f0 = up2(ac0), f1 = up2(ac1), f2 = up2(ac2), f3 = up2(ac3);
                hg_sh[r][jg] = bias + ((f0.x + f0.y) + (f1.x + f1.y))
                                    + ((f2.x + f2.y) + (f3.x + f3.y));
            }
        }
        if (s < 511 && tid < 160) {
            int r = tid / 20, k = tid - r * 20;
            x_sh[cur ^ 1][r][k] = pf0;
        }
        __syncthreads();
        if (isC) {
            float gi = xg_sh[r0][j0]      + hg_sh[r0][j0];
            float gf = xg_sh[r0][30 + j0] + hg_sh[r0][30 + j0];
            float gg = xg_sh[r0][60 + j0] + hg_sh[r0][60 + j0];
            float go = xg_sh[r0][90 + j0] + hg_sh[r0][90 + j0];
            cc0 = sigm(gf) * cc0 + sigm(gi) * tanh_f(gg);
            float hh = sigm(go) * tanh_f(cc0);
            h_sh[cur ^ 1][r0][j0] = hh;
            outp[(t * 512 + (rowBase + r0)) * 30 + j0] = hh;
        }
        __syncthreads();
        cur ^= 1;
    }
}

// ---------------------------------------------------------------------------
// Layer 2: 128 blocks (2 dirs x 64), 8 rho-rows/block, 448 threads.
//   tid [0,200)    : x-part gate j = tid      (Wih row, 30 u64 regs)
//   tid [224,424)  : h-part gate j = tid-224  (Whh row, 25 u64 regs, + bias)
//   combine: 400 tasks on tid < 400
// ---------------------------------------------------------------------------
__global__ void __launch_bounds__(448, 1) r2_kernel(
    const float* __restrict__ h0f, const float* __restrict__ c0f,
    const float* __restrict__ Wihf, const float* __restrict__ Whhf,
    const float* __restrict__ bihf, const float* __restrict__ bhhf,
    const float* __restrict__ h0b, const float* __restrict__ c0b,
    const float* __restrict__ Wihb, const float* __restrict__ Whhb,
    const float* __restrict__ bihb, const float* __restrict__ bhhb)
{
    const int dir = blockIdx.x >> 6;
    const int rowBase = (blockIdx.x & 63) * 8;
    const float* Wih = dir ? Wihb : Wihf;
    const float* Whh = dir ? Whhb : Whhf;
    const float* bih = dir ? bihb : bihf;
    const float* bhh = dir ? bhhb : bhhf;
    const float* h0  = dir ? h0b  : h0f;
    const float* c0  = dir ? c0b  : c0f;

    const int tid = threadIdx.x;
    __shared__ __align__(16) float h_sh[2][8][52];
    __shared__ __align__(16) float x_sh[2][8][60];
    __shared__ float xg_sh[8][200];
    __shared__ float hg_sh[8][200];

    const bool isX = (tid < 200);
    const bool isH = (tid >= 224 && tid < 424);
    const int  jg  = isX ? tid : (tid - 224);

    u64 wih2[30], whh2[25];
    float bias = 0.f;
    if (isX) {
        const u64* wa = (const u64*)(Wih + jg * 60);    // 240B rows, 8B-aligned
#pragma unroll
        for (int k = 0; k < 30; k++) wih2[k] = wa[k];
    }
    if (isH) {
        const u64* wb = (const u64*)(Whh + jg * 50);    // 200B rows, 8B-aligned
#pragma unroll
        for (int k = 0; k < 25; k++) whh2[k] = wb[k];
        bias = bih[jg] + bhh[jg];
    }
    for (int idx = tid; idx < 8 * 52; idx += 448) {
        int r = idx / 52, k = idx - r * 52;
        h_sh[0][r][k] = (k < 50) ? h0[(rowBase + r) * 50 + k] : 0.f;
        h_sh[1][r][k] = 0.f;
    }
    // combine: task m = tid in [0,400): r = m/50, j = m%50
    const int r0 = tid / 50, j0 = tid - r0 * 50;
    const bool isC = (tid < 400);
    float cc0 = isC ? c0[(rowBase + r0) * 50 + j0] : 0.f;

    {   // preload layer-2 inputs for step 0
        int u0 = dir ? 511 : 0;
        for (int idx = tid; idx < 480; idx += 448) {
            int r = idx / 60, k = idx - r * 60;
            int rho = rowBase + r;
            x_sh[0][r][k] = (k < 30)
                ? g_F1[(rho * 512 + u0) * 30 + k]
                : g_B1[((511 - rho) * 512 + u0) * 30 + (k - 30)];
        }
    }
    __syncthreads();

    int cur = 0;
    for (int s = 0; s < 512; s++) {
        const int u = dir ? (511 - s) : s;
        float pf[2] = {0.f, 0.f};
        if (s < 511) {
            int un = dir ? (510 - s) : (s + 1);
#pragma unroll
            for (int i = 0; i < 2; i++) {
                int idx = tid + i * 448;
                if (idx < 480) {
                    int r = idx / 60, k = idx - r * 60;
                    int rho = rowBase + r;
                    pf[i] = (k < 30)
                        ? g_F1[(rho * 512 + un) * 30 + k]
                        : g_B1[((511 - rho) * 512 + un) * 30 + (k - 30)];
                }
            }
        }
        if (isX) {
#pragma unroll 2
            for (int r = 0; r < 8; r++) {
                const ulonglong2* xs = (const ulonglong2*)x_sh[cur][r];
                u64 ac0 = 0, ac1 = 0, ac2 = 0, ac3 = 0;
#pragma unroll
                for (int q = 0; q < 15; q++) {
                    ulonglong2 v = xs[q];
                    if (q & 1) { fma2(ac2, v.x, wih2[2 * q]); fma2(ac3, v.y, wih2[2 * q + 1]); }
                    else        { fma2(ac0, v.x, wih2[2 * q]); fma2(ac1, v.y, wih2[2 * q + 1]); }
                }
                float2 f0 = up2(ac0), f1 = up2(ac1), f2 = up2(ac2), f3 = up2(ac3);
                xg_sh[r][jg] = ((f0.x + f0.y) + (f1.x + f1.y))
                             + ((f2.x + f2.y) + (f3.x + f3.y));
            }
        } else if (isH) {
#pragma unroll 2
            for (int r = 0; r < 8; r++) {
                const ulonglong2* hs = (const ulonglong2*)h_sh[cur][r];
                u64 ac0 = 0, ac1 = 0, ac2 = 0, ac3 = 0;
#pragma unroll
                for (int q = 0; q < 12; q++) {
                    ulonglong2 v = hs[q];
                    if (q & 1) { fma2(ac2, v.x, whh2[2 * q]); fma2(ac3, v.y, whh2[2 * q + 1]); }
                    else        { fma2(ac0, v.x, whh2[2 * q]); fma2(ac1, v.y, whh2[2 * q + 1]); }
                }
                {
                    u64 tpair = *(const u64*)&h_sh[cur][r][48];
                    fma2(ac0, tpair, whh2[24]);
                }
                float2 f0 = up2(ac0), f1 = up2(ac1), f2 = up2(ac2), f3 = up2(ac3);
                hg_sh[r][jg] = bias + ((f0.x + f0.y) + (f1.x + f1.y))
                                    + ((f2.x + f2.y) + (f3.x + f3.y));
            }
        }
        if (s < 511) {
#pragma unroll
            for (int i = 0; i < 2; i++) {
                int idx = tid + i * 448;
                if (idx < 480) {
                    int r = idx / 60, k = idx - r * 60;
                    x_sh[cur ^ 1][r][k] = pf[i];
                }
            }
        }
        __syncthreads();
        if (isC) {
            float gi = xg_sh[r0][j0]       + hg_sh[r0][j0];
            float gf = xg_sh[r0][50 + j0]  + hg_sh[r0][50 + j0];
            float gg = xg_sh[r0][100 + j0] + hg_sh[r0][100 + j0];
            float go = xg_sh[r0][150 + j0] + hg_sh[r0][150 + j0];
            cc0 = sigm(gf) * cc0 + sigm(gi) * tanh_f(gg);
            float hh = sigm(go) * tanh_f(cc0);
            h_sh[cur ^ 1][r0][j0] = hh;
            int rho = rowBase + r0;
            if (dir == 0) g_F2[(u * 512 + rho) * 50 + j0] = hh;
            else          g_B2[((511 - u) * 512 + rho) * 50 + j0] = hh;
        }
        __syncthreads();
        cur ^= 1;
    }
}

// ---------------------------------------------------------------------------
// Output linear: out[pos][n] = F2[pos]·wf[n] + B2[pos]·wb[n] + b[n]
// Thread per position, 45 accumulators. Weight halves in separate shared
// arrays, row stride 52 floats (208B = 13*16) so every row is 16B-aligned.
// ---------------------------------------------------------------------------
__global__ void __launch_bounds__(256) out_kernel(
    const float* __restrict__ lin_w, const float* __restrict__ lin_b,
    float* __restrict__ out)
{
    __shared__ __align__(16) float wf_sh[45 * 52];
    __shared__ __align__(16) float wb_sh[45 * 52];
    __shared__ float b_sh[45];
    const int tid = threadIdx.x;
    for (int i = tid; i < 45 * 52; i += 256) {
        int n = i / 52, k = i - n * 52;
        wf_sh[i] = (k < 50) ? lin_w[n * 100 + k] : 0.f;
        wb_sh[i] = (k < 50) ? lin_w[n * 100 + 50 + k] : 0.f;
    }
    if (tid < 45) b_sh[tid] = lin_b[tid];
    __syncthreads();

    const int pos = blockIdx.x * 256 + tid;
    float acc[45];
#pragma unroll
    for (int n = 0; n < 45; n++) acc[n] = b_sh[n];

    {
        const float* p = g_F2 + (long)pos * 50;
        float xr[50];
#pragma unroll
        for (int k = 0; k < 50; k++) xr[k] = p[k];
        for (int n = 0; n < 45; n++) {
            const float* w = wf_sh + n * 52;
            float a0 = 0.f, a1 = 0.f, a2 = 0.f, a3 = 0.f;
#pragma unroll
            for (int k = 0; k < 48; k += 4) {
                float4 wv = *(const float4*)(w + k);
                a0 += xr[k]     * wv.x;
                a1 += xr[k + 1] * wv.y;
                a2 += xr[k + 2] * wv.z;
                a3 += xr[k + 3] * wv.w;
            }
            a0 += xr[48] * w[48];
            a1 += xr[49] * w[49];
            acc[n] += (a0 + a1) + (a2 + a3);
        }
    }
    {
        const float* p = g_B2 + (long)pos * 50;
        float xr[50];
#pragma unroll
        for (int k = 0; k < 50; k++) xr[k] = p[k];
        for (int n = 0; n < 45; n++) {
            const float* w = wb_sh + n * 52;
            float a0 = 0.f, a1 = 0.f, a2 = 0.f, a3 = 0.f;
#pragma unroll
            for (int k = 0; k < 48; k += 4) {
                float4 wv = *(const float4*)(w + k);
                a0 += xr[k]     * wv.x;
                a1 += xr[k + 1] * wv.y;
                a2 += xr[k + 2] * wv.z;
                a3 += xr[k + 3] * wv.w;
            }
            a0 += xr[48] * w[48];
            a1 += xr[49] * w[49];
            acc[n] += (a0 + a1) + (a2 + a3);
        }
    }
    float* o = out + (long)pos * 45;
#pragma unroll
    for (int n = 0; n < 45; n++) o[n] = acc[n];
}

// ---------------------------------------------------------------------------
extern "C" void kernel_launch(void* const* d_in, const int* in_sizes, int n_in,
                              void* d_out, int out_size) {
    const int*   x       = (const int*)  d_in[0];
    const float* emb_f1  = (const float*)d_in[1];
    const float* emb_b1  = (const float*)d_in[2];
    const float* h0_f1   = (const float*)d_in[3];
    const float* c0_f1   = (const float*)d_in[4];
    const float* Wih_f1  = (const float*)d_in[5];
    const float* Whh_f1  = (const float*)d_in[6];
    const float* bih_f1  = (const float*)d_in[7];
    const float* bhh_f1  = (const float*)d_in[8];
    const float* h0_b1   = (const float*)d_in[9];
    const float* c0_b1   = (const float*)d_in[10];
    const float* Wih_b1  = (const float*)d_in[11];
    const float* Whh_b1  = (const float*)d_in[12];
    const float* bih_b1  = (const float*)d_in[13];
    const float* bhh_b1  = (const float*)d_in[14];
    const float* h0_f2   = (const float*)d_in[15];
    const float* c0_f2   = (const float*)d_in[16];
    const float* Wih_f2  = (const float*)d_in[17];
    const float* Whh_f2  = (const float*)d_in[18];
    const float* bih_f2  = (const float*)d_in[19];
    const float* bhh_f2  = (const float*)d_in[20];
    const float* h0_b2   = (const float*)d_in[21];
    const float* c0_b2   = (const float*)d_in[22];
    const float* Wih_b2  = (const float*)d_in[23];
    const float* Whh_b2  = (const float*)d_in[24];
    const float* bih_b2  = (const float*)d_in[25];
    const float* bhh_b2  = (const float*)d_in[26];
    const float* lin_w   = (const float*)d_in[27];
    const float* lin_b   = (const float*)d_in[28];
    float* out = (float*)d_out;

    detect_kernel<<<1, 1>>>(x);
    convert_kernel<<<1024, 256>>>(x);
    r1_kernel<<<128, 256>>>(emb_f1, emb_b1,
                            h0_f1, c0_f1, Wih_f1, Whh_f1, bih_f1, bhh_f1,
                            h0_b1, c0_b1, Wih_b1, Whh_b1, bih_b1, bhh_b1);
    r2_kernel<<<128, 448>>>(h0_f2, c0_f2, Wih_f2, Whh_f2, bih_f2, bhh_f2,
                            h0_b2, c0_b2, Wih_b2, Whh_b2, bih_b2, bhh_b2);
    out_kernel<<<1024, 256>>>(lin_w, lin_b, out);
}

// round 6
// speedup vs baseline: 1.2555x; 1.2555x over previous
#include <cuda_runtime.h>
#include <cuda_bf16.h>

// ---------------------------------------------------------------------------
// Tagger: 2-layer bidirectional LSTM (B=S=512, E=20, H1=30, H2=50, NTAGS=45)
// Reference quirk: (S,B,H)->(B,S,H) reshape with S==B is an index swap.
// Storage convention (all [time][batch][h]):
//   F1[t][b], B1[t][b]  : layer-1 hidden at time t, batch b
//   layer-2 row rho consumes at step u: ( F1[rho][u], B1[511-rho][u] )
//   F2 stored [u][rho]; B2 stored [511-u][rho]  =>  OUT reads both at [i][j].
//
// Non-recurrent work is hoisted out of the scans:
//   TG[dir][tok][120]  = Wih1 · emb[tok]            (token gate table)
//   XG[dir][rho*512+u][200] = Wih2 · (F1[rho][u], B1[511-rho][u])
// The scan kernels compute only Whh·h (+bias) and fuse with prefetched
// TG/XG values in the combine phase.
// ---------------------------------------------------------------------------

typedef unsigned long long u64;

__device__ float g_F1[512 * 512 * 30];
__device__ float g_B1[512 * 512 * 30];
__device__ float g_F2[512 * 512 * 50];
__device__ float g_B2[512 * 512 * 50];
__device__ float g_TGf[50000 * 120];
__device__ float g_TGb[50000 * 120];
__device__ float g_XGf[512 * 512 * 200];
__device__ float g_XGb[512 * 512 * 200];
__device__ int   g_xidx[512 * 512];
__device__ int   g_is64;

__device__ __forceinline__ void fma2(u64 &acc, u64 a, u64 b) {
    asm("fma.rn.f32x2 %0, %1, %2, %0;" : "+l"(acc) : "l"(a), "l"(b));
}
__device__ __forceinline__ float2 up2(u64 v) {
    float2 r; asm("mov.b64 {%0, %1}, %2;" : "=f"(r.x), "=f"(r.y) : "l"(v));
    return r;
}

__device__ __forceinline__ float sigm(float x) {
    return __fdividef(1.f, 1.f + __expf(-x));
}
__device__ __forceinline__ float tanh_f(float x) {
    float a = fabsf(x);
    float e = __expf(-2.f * a);
    float t = __fdividef(1.f - e, 1.f + e);
    return x < 0.f ? -t : t;
}

// x may arrive as int32 (JAX default) or int64 (reference dtype). If int64,
// all odd 32-bit words are zero (tokens < 50000).
__global__ void detect_kernel(const int* __restrict__ xr) {
    int z = 0;
    for (int i = 1; i < 256; i += 2) z |= xr[i];
    g_is64 = (z == 0) ? 1 : 0;
}

__global__ void convert_kernel(const int* __restrict__ xr) {
    int i = blockIdx.x * blockDim.x + threadIdx.x;
    int is64 = g_is64;
    if (i < 512 * 512) g_xidx[i] = is64 ? xr[2 * i] : xr[i];
}

// ---------------------------------------------------------------------------
// Token gate table: TG[tok][j] = Wih1[j] · emb[tok]   (j < 120)
// ---------------------------------------------------------------------------
__global__ void __launch_bounds__(256) tokgate_kernel(
    const float* __restrict__ emb, const float* __restrict__ Wih,
    int dir, int nvocab)
{
    float* TG = dir ? g_TGb : g_TGf;
    __shared__ __align__(16) float e_sh[256][20];
    const int tid = threadIdx.x;
    const int base = blockIdx.x * 256;
    for (int idx = tid; idx < 256 * 20; idx += 256) {
        int tl = idx / 20, k = idx - tl * 20;
        int tok = base + tl;
        e_sh[tl][k] = (tok < nvocab) ? emb[tok * 20 + k] : 0.f;
    }
    __syncthreads();
    if (tid < 120) {
        u64 w2[10];
        const u64* wa = (const u64*)(Wih + tid * 20);
#pragma unroll
        for (int k = 0; k < 10; k++) w2[k] = wa[k];
        int nmax = nvocab - base; if (nmax > 256) nmax = 256;
        for (int tl = 0; tl < nmax; tl++) {
            const ulonglong2* xs = (const ulonglong2*)e_sh[tl];
            u64 ac0 = 0, ac1 = 0, ac2 = 0, ac3 = 0;
#pragma unroll
            for (int q = 0; q < 5; q++) {
                ulonglong2 v = xs[q];
                if (q & 1) { fma2(ac2, v.x, w2[2 * q]); fma2(ac3, v.y, w2[2 * q + 1]); }
                else        { fma2(ac0, v.x, w2[2 * q]); fma2(ac1, v.y, w2[2 * q + 1]); }
            }
            float2 f0 = up2(ac0), f1 = up2(ac1), f2 = up2(ac2), f3 = up2(ac3);
            TG[(base + tl) * 120 + tid] = ((f0.x + f0.y) + (f1.x + f1.y))
                                        + ((f2.x + f2.y) + (f3.x + f3.y));
        }
    }
}

// ---------------------------------------------------------------------------
// Layer-2 input gates: XG[rho*512+u][j] = Wih2[j] · (F1[rho][u], B1[511-rho][u])
// grid = 8192: dir = bx>>12, rho = (bx&4095)>>3, u-chunk = (bx&7)*64
// ---------------------------------------------------------------------------
__global__ void __launch_bounds__(256) xg2_kernel(
    const float* __restrict__ Wihf, const float* __restrict__ Wihb)
{
    const int bx = blockIdx.x;
    const int dir = bx >> 12;
    const int rem = bx & 4095;
    const int rho = rem >> 3;
    const int u0  = (rem & 7) * 64;
    const float* Wih = dir ? Wihb : Wihf;
    float* XG = dir ? g_XGb : g_XGf;

    __shared__ __align__(16) float x_sh[64][60];
    const int tid = threadIdx.x;
    const float* f1 = g_F1 + ((size_t)rho * 512 + u0) * 30;
    const float* b1 = g_B1 + ((size_t)(511 - rho) * 512 + u0) * 30;
    for (int idx = tid; idx < 1920; idx += 256) {
        int r = idx / 30, k = idx - r * 30;
        x_sh[r][k]      = f1[idx];
        x_sh[r][30 + k] = b1[idx];
    }
    __syncthreads();
    if (tid < 200) {
        u64 w2[30];
        const u64* wa = (const u64*)(Wih + tid * 60);
#pragma unroll
        for (int k = 0; k < 30; k++) w2[k] = wa[k];
        float* outb = XG + ((size_t)rho * 512 + u0) * 200 + tid;
#pragma unroll 2
        for (int p = 0; p < 64; p++) {
            const ulonglong2* xs = (const ulonglong2*)x_sh[p];
            u64 ac0 = 0, ac1 = 0, ac2 = 0, ac3 = 0;
#pragma unroll
            for (int q = 0; q < 15; q++) {
                ulonglong2 v = xs[q];
                if (q & 1) { fma2(ac2, v.x, w2[2 * q]); fma2(ac3, v.y, w2[2 * q + 1]); }
                else        { fma2(ac0, v.x, w2[2 * q]); fma2(ac1, v.y, w2[2 * q + 1]); }
            }
            float2 f0 = up2(ac0), f1v = up2(ac1), f2 = up2(ac2), f3 = up2(ac3);
            outb[p * 200] = ((f0.x + f0.y) + (f1v.x + f1v.y))
                          + ((f2.x + f2.y) + (f3.x + f3.y));
        }
    }
}

// ---------------------------------------------------------------------------
// Layer 1 scan: 128 blocks (2 dirs x 64), 8 batch rows/block, 128 threads.
// Gate threads tid<120 compute ONLY Whh·h + bias. Combine (240 tasks, 2/thread)
// adds prefetched token-gate values from TG.
// ---------------------------------------------------------------------------
__global__ void __launch_bounds__(128, 1) r1_kernel(
    const float* __restrict__ h0f, const float* __restrict__ c0f,
    const float* __restrict__ Whhf,
    const float* __restrict__ bihf, const float* __restrict__ bhhf,
    const float* __restrict__ h0b, const float* __restrict__ c0b,
    const float* __restrict__ Whhb,
    const float* __restrict__ bihb, const float* __restrict__ bhhb)
{
    const int dir = blockIdx.x >> 6;           // 0 = forward, 1 = backward
    const int rowBase = (blockIdx.x & 63) * 8;
    const float* Whh = dir ? Whhb : Whhf;
    const float* bih = dir ? bihb : bihf;
    const float* bhh = dir ? bhhb : bhhf;
    const float* h0  = dir ? h0b  : h0f;
    const float* c0  = dir ? c0b  : c0f;
    const float* TG  = dir ? g_TGb : g_TGf;
    float* outp = dir ? g_B1 : g_F1;

    const int tid = threadIdx.x;
    __shared__ __align__(16) float h_sh[2][8][32];
    __shared__ float hg_sh[8][120];

    const bool isH = (tid < 120);
    u64 whh2[15];
    float bias = 0.f;
    if (isH) {
        const u64* wb = (const u64*)(Whh + tid * 30);   // 120B rows, 8B-aligned
#pragma unroll
        for (int k = 0; k < 15; k++) whh2[k] = wb[k];
        bias = bih[tid] + bhh[tid];
    }
    for (int idx = tid; idx < 8 * 32; idx += 128) {
        int r = idx >> 5, k = idx & 31;
        h_sh[0][r][k] = (k < 30) ? h0[(rowBase + r) * 30 + k] : 0.f;
        h_sh[1][r][k] = 0.f;
    }
    // combine: tasks m0 = tid, m1 = tid+128 (valid if < 240)
    const int m1 = tid + 128;
    const int r0 = tid / 30, j0 = tid - r0 * 30;
    const int r1 = m1 / 30,  j1 = m1 - r1 * 30;
    const bool has1 = (m1 < 240);
    float cc0 = c0[(rowBase + r0) * 30 + j0];
    float cc1 = has1 ? c0[(rowBase + r1) * 30 + j1] : 0.f;

    // prefetch token gates for step 0
    float tg0[4] = {0,0,0,0}, tg1[4] = {0,0,0,0};
    {
        int t0 = dir ? 511 : 0;
        int tok = g_xidx[(rowBase + r0) * 512 + t0];
#pragma unroll
        for (int g = 0; g < 4; g++) tg0[g] = TG[tok * 120 + g * 30 + j0];
        if (has1) {
            int tk = g_xidx[(rowBase + r1) * 512 + t0];
#pragma unroll
            for (int g = 0; g < 4; g++) tg1[g] = TG[tk * 120 + g * 30 + j1];
        }
    }
    __syncthreads();

    int cur = 0;
    for (int s = 0; s < 512; s++) {
        const int t = dir ? (511 - s) : s;
        // prefetch next step's token gates (hidden under gate FMA stretch)
        float ntg0[4] = {0,0,0,0}, ntg1[4] = {0,0,0,0};
        if (s < 511) {
            int tn = dir ? (510 - s) : (s + 1);
            int tok = g_xidx[(rowBase + r0) * 512 + tn];
#pragma unroll
            for (int g = 0; g < 4; g++) ntg0[g] = TG[tok * 120 + g * 30 + j0];
            if (has1) {
                int tk = g_xidx[(rowBase + r1) * 512 + tn];
#pragma unroll
                for (int g = 0; g < 4; g++) ntg1[g] = TG[tk * 120 + g * 30 + j1];
            }
        }
        if (isH) {
#pragma unroll 2
            for (int r = 0; r < 8; r++) {
                const ulonglong2* hs = (const ulonglong2*)h_sh[cur][r];
                u64 ac0 = 0, ac1 = 0, ac2 = 0, ac3 = 0;
#pragma unroll
                for (int q = 0; q < 7; q++) {
                    ulonglong2 v = hs[q];
                    if (q & 1) { fma2(ac2, v.x, whh2[2 * q]); fma2(ac3, v.y, whh2[2 * q + 1]); }
                    else        { fma2(ac0, v.x, whh2[2 * q]); fma2(ac1, v.y, whh2[2 * q + 1]); }
                }
                {
                    u64 tpair = *(const u64*)&h_sh[cur][r][28];
                    fma2(ac2, tpair, whh2[14]);
                }
                float2 f0 = up2(ac0), f1 = up2(ac1), f2 = up2(ac2), f3 = up2(ac3);
                hg_sh[r][tid] = bias + ((f0.x + f0.y) + (f1.x + f1.y))
                                     + ((f2.x + f2.y) + (f3.x + f3.y));
            }
        }
        __syncthreads();
        {
            float gi = tg0[0] + hg_sh[r0][j0];
            float gf = tg0[1] + hg_sh[r0][30 + j0];
            float gg = tg0[2] + hg_sh[r0][60 + j0];
            float go = tg0[3] + hg_sh[r0][90 + j0];
            cc0 = sigm(gf) * cc0 + sigm(gi) * tanh_f(gg);
            float hh = sigm(go) * tanh_f(cc0);
            h_sh[cur ^ 1][r0][j0] = hh;
            outp[(t * 512 + (rowBase + r0)) * 30 + j0] = hh;
        }
        if (has1) {
            float gi = tg1[0] + hg_sh[r1][j1];
            float gf = tg1[1] + hg_sh[r1][30 + j1];
            float gg = tg1[2] + hg_sh[r1][60 + j1];
            float go = tg1[3] + hg_sh[r1][90 + j1];
            cc1 = sigm(gf) * cc1 + sigm(gi) * tanh_f(gg);
            float hh = sigm(go) * tanh_f(cc1);
            h_sh[cur ^ 1][r1][j1] = hh;
            outp[(t * 512 + (rowBase + r1)) * 30 + j1] = hh;
        }
        __syncthreads();
#pragma unroll
        for (int g = 0; g < 4; g++) { tg0[g] = ntg0[g]; tg1[g] = ntg1[g]; }
        cur ^= 1;
    }
}

// ---------------------------------------------------------------------------
// Layer 2 scan: 128 blocks (2 dirs x 64), 8 rho-rows/block, 224 threads.
// Gate threads tid<200 compute ONLY Whh·h + bias. Combine (400 tasks, 2/thread)
// adds prefetched XG values.
// ---------------------------------------------------------------------------
__global__ void __launch_bounds__(224, 1) r2_kernel(
    const float* __restrict__ h0f, const float* __restrict__ c0f,
    const float* __restrict__ Whhf,
    const float* __restrict__ bihf, const float* __restrict__ bhhf,
    const float* __restrict__ h0b, const float* __restrict__ c0b,
    const float* __restrict__ Whhb,
    const float* __restrict__ bihb, const float* __restrict__ bhhb)
{
    const int dir = blockIdx.x >> 6;
    const int rowBase = (blockIdx.x & 63) * 8;
    const float* Whh = dir ? Whhb : Whhf;
    const float* bih = dir ? bihb : bihf;
    const float* bhh = dir ? bhhb : bhhf;
    const float* h0  = dir ? h0b  : h0f;
    const float* c0  = dir ? c0b  : c0f;
    const float* XG  = dir ? g_XGb : g_XGf;

    const int tid = threadIdx.x;
    __shared__ __align__(16) float h_sh[2][8][52];
    __shared__ float hg_sh[8][200];

    const bool isH = (tid < 200);
    u64 whh2[25];
    float bias = 0.f;
    if (isH) {
        const u64* wb = (const u64*)(Whh + tid * 50);   // 200B rows, 8B-aligned
#pragma unroll
        for (int k = 0; k < 25; k++) whh2[k] = wb[k];
        bias = bih[tid] + bhh[tid];
    }
    for (int idx = tid; idx < 8 * 52; idx += 224) {
        int r = idx / 52, k = idx - r * 52;
        h_sh[0][r][k] = (k < 50) ? h0[(rowBase + r) * 50 + k] : 0.f;
        h_sh[1][r][k] = 0.f;
    }
    // combine: tasks m0 = tid, m1 = tid+224 (valid if < 400)
    const int m1 = tid + 224;
    const int r0 = tid / 50, j0 = tid - r0 * 50;
    const int r1 = m1 / 50,  j1 = m1 - r1 * 50;
    const bool has1 = (m1 < 400);
    float cc0 = c0[(rowBase + r0) * 50 + j0];
    float cc1 = has1 ? c0[(rowBase + r1) * 50 + j1] : 0.f;
    const size_t xb0 = ((size_t)(rowBase + r0) * 512) * 200 + j0;
    const size_t xb1 = has1 ? ((size_t)(rowBase + r1) * 512) * 200 + j1 : 0;

    // prefetch XG for step 0
    float xg0[4] = {0,0,0,0}, xg1[4] = {0,0,0,0};
    {
        int u0 = dir ? 511 : 0;
#pragma unroll
        for (int g = 0; g < 4; g++) xg0[g] = XG[xb0 + (size_t)u0 * 200 + g * 50];
        if (has1) {
#pragma unroll
            for (int g = 0; g < 4; g++) xg1[g] = XG[xb1 + (size_t)u0 * 200 + g * 50];
        }
    }
    __syncthreads();

    int cur = 0;
    for (int s = 0; s < 512; s++) {
        const int u = dir ? (511 - s) : s;
        float nxg0[4] = {0,0,0,0}, nxg1[4] = {0,0,0,0};
        if (s < 511) {
            int un = dir ? (510 - s) : (s + 1);
#pragma unroll
            for (int g = 0; g < 4; g++) nxg0[g] = XG[xb0 + (size_t)un * 200 + g * 50];
            if (has1) {
#pragma unroll
                for (int g = 0; g < 4; g++) nxg1[g] = XG[xb1 + (size_t)un * 200 + g * 50];
            }
        }
        if (isH) {
#pragma unroll 2
            for (int r = 0; r < 8; r++) {
                const ulonglong2* hs = (const ulonglong2*)h_sh[cur][r];
                u64 ac0 = 0, ac1 = 0, ac2 = 0, ac3 = 0;
#pragma unroll
                for (int q = 0; q < 12; q++) {
                    ulonglong2 v = hs[q];
                    if (q & 1) { fma2(ac2, v.x, whh2[2 * q]); fma2(ac3, v.y, whh2[2 * q + 1]); }
                    else        { fma2(ac0, v.x, whh2[2 * q]); fma2(ac1, v.y, whh2[2 * q + 1]); }
                }
                {
                    u64 tpair = *(const u64*)&h_sh[cur][r][48];
                    fma2(ac0, tpair, whh2[24]);
                }
                float2 f0 = up2(ac0), f1 = up2(ac1), f2 = up2(ac2), f3 = up2(ac3);
                hg_sh[r][tid] = bias + ((f0.x + f0.y) + (f1.x + f1.y))
                                     + ((f2.x + f2.y) + (f3.x + f3.y));
            }
        }
        __syncthreads();
        {
            float gi = xg0[0] + hg_sh[r0][j0];
            float gf = xg0[1] + hg_sh[r0][50 + j0];
            float gg = xg0[2] + hg_sh[r0][100 + j0];
            float go = xg0[3] + hg_sh[r0][150 + j0];
            cc0 = sigm(gf) * cc0 + sigm(gi) * tanh_f(gg);
            float hh = sigm(go) * tanh_f(cc0);
            h_sh[cur ^ 1][r0][j0] = hh;
            int rho = rowBase + r0;
            if (dir == 0) g_F2[((size_t)u * 512 + rho) * 50 + j0] = hh;
            else          g_B2[((size_t)(511 - u) * 512 + rho) * 50 + j0] = hh;
        }
        if (has1) {
            float gi = xg1[0] + hg_sh[r1][j1];
            float gf = xg1[1] + hg_sh[r1][50 + j1];
            float gg = xg1[2] + hg_sh[r1][100 + j1];
            float go = xg1[3] + hg_sh[r1][150 + j1];
            cc1 = sigm(gf) * cc1 + sigm(gi) * tanh_f(gg);
            float hh = sigm(go) * tanh_f(cc1);
            h_sh[cur ^ 1][r1][j1] = hh;
            int rho = rowBase + r1;
            if (dir == 0) g_F2[((size_t)u * 512 + rho) * 50 + j1] = hh;
            else          g_B2[((size_t)(511 - u) * 512 + rho) * 50 + j1] = hh;
        }
        __syncthreads();
#pragma unroll
        for (int g = 0; g < 4; g++) { xg0[g] = nxg0[g]; xg1[g] = nxg1[g]; }
        cur ^= 1;
    }
}

// ---------------------------------------------------------------------------
// Output linear: out[pos][n] = F2[pos]·wf[n] + B2[pos]·wb[n] + b[n]
// ---------------------------------------------------------------------------
__global__ void __launch_bounds__(256) out_kernel(
    const float* __restrict__ lin_w, const float* __restrict__ lin_b,
    float* __restrict__ out)
{
    __shared__ __align__(16) float wf_sh[45 * 52];
    __shared__ __align__(16) float wb_sh[45 * 52];
    __shared__ float b_sh[45];
    const int tid = threadIdx.x;
    for (int i = tid; i < 45 * 52; i += 256) {
        int n = i / 52, k = i - n * 52;
        wf_sh[i] = (k < 50) ? lin_w[n * 100 + k] : 0.f;
        wb_sh[i] = (k < 50) ? lin_w[n * 100 + 50 + k] : 0.f;
    }
    if (tid < 45) b_sh[tid] = lin_b[tid];
    __syncthreads();

    const int pos = blockIdx.x * 256 + tid;
    float acc[45];
#pragma unroll
    for (int n = 0; n < 45; n++) acc[n] = b_sh[n];

    {
        const float* p = g_F2 + (size_t)pos * 50;
        float xr[50];
#pragma unroll
        for (int k = 0; k < 50; k++) xr[k] = p[k];
        for (int n = 0; n < 45; n++) {
            const float* w = wf_sh + n * 52;
            float a0 = 0.f, a1 = 0.f, a2 = 0.f, a3 = 0.f;
#pragma unroll
            for (int k = 0; k < 48; k += 4) {
                float4 wv = *(const float4*)(w + k);
                a0 += xr[k]     * wv.x;
                a1 += xr[k + 1] * wv.y;
                a2 += xr[k + 2] * wv.z;
                a3 += xr[k + 3] * wv.w;
            }
            a0 += xr[48] * w[48];
            a1 += xr[49] * w[49];
            acc[n] += (a0 + a1) + (a2 + a3);
        }
    }
    {
        const float* p = g_B2 + (size_t)pos * 50;
        float xr[50];
#pragma unroll
        for (int k = 0; k < 50; k++) xr[k] = p[k];
        for (int n = 0; n < 45; n++) {
            const float* w = wb_sh + n * 52;
            float a0 = 0.f, a1 = 0.f, a2 = 0.f, a3 = 0.f;
#pragma unroll
            for (int k = 0; k < 48; k += 4) {
                float4 wv = *(const float4*)(w + k);
                a0 += xr[k]     * wv.x;
                a1 += xr[k + 1] * wv.y;
                a2 += xr[k + 2] * wv.z;
                a3 += xr[k + 3] * wv.w;
            }
            a0 += xr[48] * w[48];
            a1 += xr[49] * w[49];
            acc[n] += (a0 + a1) + (a2 + a3);
        }
    }
    float* o = out + (size_t)pos * 45;
#pragma unroll
    for (int n = 0; n < 45; n++) o[n] = acc[n];
}

// ---------------------------------------------------------------------------
extern "C" void kernel_launch(void* const* d_in, const int* in_sizes, int n_in,
                              void* d_out, int out_size) {
    const int*   x       = (const int*)  d_in[0];
    const float* emb_f1  = (const float*)d_in[1];
    const float* emb_b1  = (const float*)d_in[2];
    const float* h0_f1   = (const float*)d_in[3];
    const float* c0_f1   = (const float*)d_in[4];
    const float* Wih_f1  = (const float*)d_in[5];
    const float* Whh_f1  = (const float*)d_in[6];
    const float* bih_f1  = (const float*)d_in[7];
    const float* bhh_f1  = (const float*)d_in[8];
    const float* h0_b1   = (const float*)d_in[9];
    const float* c0_b1   = (const float*)d_in[10];
    const float* Wih_b1  = (const float*)d_in[11];
    const float* Whh_b1  = (const float*)d_in[12];
    const float* bih_b1  = (const float*)d_in[13];
    const float* bhh_b1  = (const float*)d_in[14];
    const float* h0_f2   = (const float*)d_in[15];
    const float* c0_f2   = (const float*)d_in[16];
    const float* Wih_f2  = (const float*)d_in[17];
    const float* Whh_f2  = (const float*)d_in[18];
    const float* bih_f2  = (const float*)d_in[19];
    const float* bhh_f2  = (const float*)d_in[20];
    const float* h0_b2   = (const float*)d_in[21];
    const float* c0_b2   = (const float*)d_in[22];
    const float* Wih_b2  = (const float*)d_in[23];
    const float* Whh_b2  = (const float*)d_in[24];
    const float* bih_b2  = (const float*)d_in[25];
    const float* bhh_b2  = (const float*)d_in[26];
    const float* lin_w   = (const float*)d_in[27];
    const float* lin_b   = (const float*)d_in[28];
    float* out = (float*)d_out;

    int nvocab = in_sizes[1] / 20;
    if (nvocab > 50000) nvocab = 50000;
    int tg_blocks = (nvocab + 255) / 256;

    detect_kernel<<<1, 1>>>(x);
    convert_kernel<<<1024, 256>>>(x);
    tokgate_kernel<<<tg_blocks, 256>>>(emb_f1, Wih_f1, 0, nvocab);
    tokgate_kernel<<<tg_blocks, 256>>>(emb_b1, Wih_b1, 1, nvocab);
    r1_kernel<<<128, 128>>>(h0_f1, c0_f1, Whh_f1, bih_f1, bhh_f1,
                            h0_b1, c0_b1, Whh_b1, bih_b1, bhh_b1);
    xg2_kernel<<<8192, 256>>>(Wih_f2, Wih_b2);
    r2_kernel<<<128, 224>>>(h0_f2, c0_f2, Whh_f2, bih_f2, bhh_f2,
                            h0_b2, c0_b2, Whh_b2, bih_b2, bhh_b2);
    out_kernel<<<1024, 256>>>(lin_w, lin_b, out);
}

// round 7
// speedup vs baseline: 1.4379x; 1.1453x over previous
#include <cuda_runtime.h>
#include <cuda_bf16.h>

// ---------------------------------------------------------------------------
// Tagger: 2-layer bidirectional LSTM (B=S=512, E=20, H1=30, H2=50, NTAGS=45)
// Reference quirk: (S,B,H)->(B,S,H) reshape with S==B is an index swap.
// Storage convention (all [time][batch][h]):
//   F1[t][b], B1[t][b]  : layer-1 hidden at time t, batch b
//   layer-2 row rho consumes at step u: ( F1[rho][u], B1[511-rho][u] )
//   F2 stored [u][rho]; B2 stored [511-u][rho]  =>  OUT reads both at [i][j].
//
// Non-recurrent work hoisted out of the scans:
//   TG[dir][tok][120]        = Wih1 · emb[tok]
//   XG[dir][rho*512+u][200]  = Wih2 · (F1[rho][u], B1[511-rho][u])
// Scan kernels compute only Whh·h (+bias), fusing prefetched TG/XG in combine.
// Scans use SMALL blocks (4 rows) at 2 blocks/SM so two independent barrier
// domains overlap: while one block waits at its BAR, the other issues.
// ---------------------------------------------------------------------------

typedef unsigned long long u64;

__device__ float g_F1[512 * 512 * 30];
__device__ float g_B1[512 * 512 * 30];
__device__ float g_F2[512 * 512 * 50];
__device__ float g_B2[512 * 512 * 50];
__device__ float g_TGf[50000 * 120];
__device__ float g_TGb[50000 * 120];
__device__ float g_XGf[512 * 512 * 200];
__device__ float g_XGb[512 * 512 * 200];
__device__ int   g_xidx[512 * 512];
__device__ int   g_is64;

__device__ __forceinline__ void fma2(u64 &acc, u64 a, u64 b) {
    asm("fma.rn.f32x2 %0, %1, %2, %0;" : "+l"(acc) : "l"(a), "l"(b));
}
__device__ __forceinline__ float2 up2(u64 v) {
    float2 r; asm("mov.b64 {%0, %1}, %2;" : "=f"(r.x), "=f"(r.y) : "l"(v));
    return r;
}

__device__ __forceinline__ float sigm(float x) {
    return __fdividef(1.f, 1.f + __expf(-x));
}
__device__ __forceinline__ float tanh_f(float x) {
    float a = fabsf(x);
    float e = __expf(-2.f * a);
    float t = __fdividef(1.f - e, 1.f + e);
    return x < 0.f ? -t : t;
}

// x may arrive as int32 (JAX default) or int64 (reference dtype). If int64,
// all odd 32-bit words are zero (tokens < 50000).
__global__ void detect_kernel(const int* __restrict__ xr) {
    int z = 0;
    for (int i = 1; i < 256; i += 2) z |= xr[i];
    g_is64 = (z == 0) ? 1 : 0;
}

__global__ void convert_kernel(const int* __restrict__ xr) {
    int i = blockIdx.x * blockDim.x + threadIdx.x;
    int is64 = g_is64;
    if (i < 512 * 512) g_xidx[i] = is64 ? xr[2 * i] : xr[i];
}

// ---------------------------------------------------------------------------
// Token gate table: TG[tok][j] = Wih1[j] · emb[tok]   (j < 120)
// ---------------------------------------------------------------------------
__global__ void __launch_bounds__(256) tokgate_kernel(
    const float* __restrict__ emb, const float* __restrict__ Wih,
    int dir, int nvocab)
{
    float* TG = dir ? g_TGb : g_TGf;
    __shared__ __align__(16) float e_sh[256][20];
    const int tid = threadIdx.x;
    const int base = blockIdx.x * 256;
    for (int idx = tid; idx < 256 * 20; idx += 256) {
        int tl = idx / 20, k = idx - tl * 20;
        int tok = base + tl;
        e_sh[tl][k] = (tok < nvocab) ? emb[tok * 20 + k] : 0.f;
    }
    __syncthreads();
    if (tid < 120) {
        u64 w2[10];
        const u64* wa = (const u64*)(Wih + tid * 20);
#pragma unroll
        for (int k = 0; k < 10; k++) w2[k] = wa[k];
        int nmax = nvocab - base; if (nmax > 256) nmax = 256;
        for (int tl = 0; tl < nmax; tl++) {
            const ulonglong2* xs = (const ulonglong2*)e_sh[tl];
            u64 ac0 = 0, ac1 = 0, ac2 = 0, ac3 = 0;
#pragma unroll
            for (int q = 0; q < 5; q++) {
                ulonglong2 v = xs[q];
                if (q & 1) { fma2(ac2, v.x, w2[2 * q]); fma2(ac3, v.y, w2[2 * q + 1]); }
                else        { fma2(ac0, v.x, w2[2 * q]); fma2(ac1, v.y, w2[2 * q + 1]); }
            }
            float2 f0 = up2(ac0), f1 = up2(ac1), f2 = up2(ac2), f3 = up2(ac3);
            TG[(base + tl) * 120 + tid] = ((f0.x + f0.y) + (f1.x + f1.y))
                                        + ((f2.x + f2.y) + (f3.x + f3.y));
        }
    }
}

// ---------------------------------------------------------------------------
// Layer-2 input gates: XG[rho*512+u][j] = Wih2[j] · (F1[rho][u], B1[511-rho][u])
// grid = 8192: dir = bx>>12, rho = (bx&4095)>>3, u-chunk = (bx&7)*64
// ---------------------------------------------------------------------------
__global__ void __launch_bounds__(256) xg2_kernel(
    const float* __restrict__ Wihf, const float* __restrict__ Wihb)
{
    const int bx = blockIdx.x;
    const int dir = bx >> 12;
    const int rem = bx & 4095;
    const int rho = rem >> 3;
    const int u0  = (rem & 7) * 64;
    const float* Wih = dir ? Wihb : Wihf;
    float* XG = dir ? g_XGb : g_XGf;

    __shared__ __align__(16) float x_sh[64][60];
    const int tid = threadIdx.x;
    const float* f1 = g_F1 + ((size_t)rho * 512 + u0) * 30;
    const float* b1 = g_B1 + ((size_t)(511 - rho) * 512 + u0) * 30;
    for (int idx = tid; idx < 1920; idx += 256) {
        int r = idx / 30, k = idx - r * 30;
        x_sh[r][k]      = f1[idx];
        x_sh[r][30 + k] = b1[idx];
    }
    __syncthreads();
    if (tid < 200) {
        u64 w2[30];
        const u64* wa = (const u64*)(Wih + tid * 60);
#pragma unroll
        for (int k = 0; k < 30; k++) w2[k] = wa[k];
        float* outb = XG + ((size_t)rho * 512 + u0) * 200 + tid;
#pragma unroll 2
        for (int p = 0; p < 64; p++) {
            const ulonglong2* xs = (const ulonglong2*)x_sh[p];
            u64 ac0 = 0, ac1 = 0, ac2 = 0, ac3 = 0;
#pragma unroll
            for (int q = 0; q < 15; q++) {
                ulonglong2 v = xs[q];
                if (q & 1) { fma2(ac2, v.x, w2[2 * q]); fma2(ac3, v.y, w2[2 * q + 1]); }
                else        { fma2(ac0, v.x, w2[2 * q]); fma2(ac1, v.y, w2[2 * q + 1]); }
            }
            float2 f0 = up2(ac0), f1v = up2(ac1), f2 = up2(ac2), f3 = up2(ac3);
            outb[p * 200] = ((f0.x + f0.y) + (f1v.x + f1v.y))
                          + ((f2.x + f2.y) + (f3.x + f3.y));
        }
    }
}

// ---------------------------------------------------------------------------
// Layer 1 scan: 256 blocks (2 dirs x 128), 4 batch rows/block, 128 threads,
// 2 blocks/SM. Gate threads tid<120 compute ONLY Whh·h + bias.
// Combine: 120 tasks, exactly 1/thread, fusing prefetched TG.
// ---------------------------------------------------------------------------
__global__ void __launch_bounds__(128, 2) r1_kernel(
    const float* __restrict__ h0f, const float* __restrict__ c0f,
    const float* __restrict__ Whhf,
    const float* __restrict__ bihf, const float* __restrict__ bhhf,
    const float* __restrict__ h0b, const float* __restrict__ c0b,
    const float* __restrict__ Whhb,
    const float* __restrict__ bihb, const float* __restrict__ bhhb)
{
    const int dir = blockIdx.x >> 7;           // 0 = forward, 1 = backward
    const int rowBase = (blockIdx.x & 127) * 4;
    const float* Whh = dir ? Whhb : Whhf;
    const float* bih = dir ? bihb : bihf;
    const float* bhh = dir ? bhhb : bhhf;
    const float* h0  = dir ? h0b  : h0f;
    const float* c0  = dir ? c0b  : c0f;
    const float* TG  = dir ? g_TGb : g_TGf;
    float* outp = dir ? g_B1 : g_F1;

    const int tid = threadIdx.x;
    __shared__ __align__(16) float h_sh[2][4][32];
    __shared__ float hg_sh[4][120];

    const bool isH = (tid < 120);
    u64 whh2[15];
    float bias = 0.f;
    if (isH) {
        const u64* wb = (const u64*)(Whh + tid * 30);   // 120B rows, 8B-aligned
#pragma unroll
        for (int k = 0; k < 15; k++) whh2[k] = wb[k];
        bias = bih[tid] + bhh[tid];
    }
    for (int idx = tid; idx < 4 * 32; idx += 128) {
        int r = idx >> 5, k = idx & 31;
        h_sh[0][r][k] = (k < 30) ? h0[(rowBase + r) * 30 + k] : 0.f;
        h_sh[1][r][k] = 0.f;
    }
    // combine: task m = tid in [0,120): r = m/30, j = m%30
    const int r0 = tid / 30, j0 = tid - r0 * 30;
    const bool isC = (tid < 120);
    float cc0 = isC ? c0[(rowBase + r0) * 30 + j0] : 0.f;

    // prefetch token gates for step 0
    float tg0[4] = {0,0,0,0};
    if (isC) {
        int t0 = dir ? 511 : 0;
        int tok = g_xidx[(rowBase + r0) * 512 + t0];
#pragma unroll
        for (int g = 0; g < 4; g++) tg0[g] = TG[tok * 120 + g * 30 + j0];
    }
    __syncthreads();

    int cur = 0;
    for (int s = 0; s < 512; s++) {
        const int t = dir ? (511 - s) : s;
        // prefetch next step's token gates (hidden under gate FMA stretch)
        float ntg0[4] = {0,0,0,0};
        if (s < 511 && isC) {
            int tn = dir ? (510 - s) : (s + 1);
            int tok = g_xidx[(rowBase + r0) * 512 + tn];
#pragma unroll
            for (int g = 0; g < 4; g++) ntg0[g] = TG[tok * 120 + g * 30 + j0];
        }
        if (isH) {
#pragma unroll
            for (int r = 0; r < 4; r++) {
                const ulonglong2* hs = (const ulonglong2*)h_sh[cur][r];
                u64 ac0 = 0, ac1 = 0, ac2 = 0, ac3 = 0;
#pragma unroll
                for (int q = 0; q < 7; q++) {
                    ulonglong2 v = hs[q];
                    if (q & 1) { fma2(ac2, v.x, whh2[2 * q]); fma2(ac3, v.y, whh2[2 * q + 1]); }
                    else        { fma2(ac0, v.x, whh2[2 * q]); fma2(ac1, v.y, whh2[2 * q + 1]); }
                }
                {
                    u64 tpair = *(const u64*)&h_sh[cur][r][28];
                    fma2(ac2, tpair, whh2[14]);
                }
                float2 f0 = up2(ac0), f1 = up2(ac1), f2 = up2(ac2), f3 = up2(ac3);
                hg_sh[r][tid] = bias + ((f0.x + f0.y) + (f1.x + f1.y))
                                     + ((f2.x + f2.y) + (f3.x + f3.y));
            }
        }
        __syncthreads();
        if (isC) {
            float gi = tg0[0] + hg_sh[r0][j0];
            float gf = tg0[1] + hg_sh[r0][30 + j0];
            float gg = tg0[2] + hg_sh[r0][60 + j0];
            float go = tg0[3] + hg_sh[r0][90 + j0];
            cc0 = sigm(gf) * cc0 + sigm(gi) * tanh_f(gg);
            float hh = sigm(go) * tanh_f(cc0);
            h_sh[cur ^ 1][r0][j0] = hh;
            outp[((size_t)t * 512 + (rowBase + r0)) * 30 + j0] = hh;
        }
        __syncthreads();
#pragma unroll
        for (int g = 0; g < 4; g++) tg0[g] = ntg0[g];
        cur ^= 1;
    }
}

// ---------------------------------------------------------------------------
// Layer 2 scan: 256 blocks (2 dirs x 128), 4 rho-rows/block, 224 threads,
// 2 blocks/SM. Gate threads tid<200 compute ONLY Whh·h + bias.
// Combine: 200 tasks, exactly 1/thread, fusing prefetched XG.
// ---------------------------------------------------------------------------
__global__ void __launch_bounds__(224, 2) r2_kernel(
    const float* __restrict__ h0f, const float* __restrict__ c0f,
    const float* __restrict__ Whhf,
    const float* __restrict__ bihf, const float* __restrict__ bhhf,
    const float* __restrict__ h0b, const float* __restrict__ c0b,
    const float* __restrict__ Whhb,
    const float* __restrict__ bihb, const float* __restrict__ bhhb)
{
    const int dir = blockIdx.x >> 7;
    const int rowBase = (blockIdx.x & 127) * 4;
    const float* Whh = dir ? Whhb : Whhf;
    const float* bih = dir ? bihb : bihf;
    const float* bhh = dir ? bhhb : bhhf;
    const float* h0  = dir ? h0b  : h0f;
    const float* c0  = dir ? c0b  : c0f;
    const float* XG  = dir ? g_XGb : g_XGf;

    const int tid = threadIdx.x;
    __shared__ __align__(16) float h_sh[2][4][52];
    __shared__ float hg_sh[4][200];

    const bool isH = (tid < 200);
    u64 whh2[25];
    float bias = 0.f;
    if (isH) {
        const u64* wb = (const u64*)(Whh + tid * 50);   // 200B rows, 8B-aligned
#pragma unroll
        for (int k = 0; k < 25; k++) whh2[k] = wb[k];
        bias = bih[tid] + bhh[tid];
    }
    for (int idx = tid; idx < 4 * 52; idx += 224) {
        int r = idx / 52, k = idx - r * 52;
        h_sh[0][r][k] = (k < 50) ? h0[(rowBase + r) * 50 + k] : 0.f;
        h_sh[1][r][k] = 0.f;
    }
    // combine: task m = tid in [0,200): r = m/50, j = m%50
    const int r0 = tid / 50, j0 = tid - r0 * 50;
    const bool isC = (tid < 200);
    float cc0 = isC ? c0[(rowBase + r0) * 50 + j0] : 0.f;
    const size_t xb0 = ((size_t)(rowBase + r0) * 512) * 200 + j0;

    // prefetch XG for step 0
    float xg0[4] = {0,0,0,0};
    if (isC) {
        int u0 = dir ? 511 : 0;
#pragma unroll
        for (int g = 0; g < 4; g++) xg0[g] = XG[xb0 + (size_t)u0 * 200 + g * 50];
    }
    __syncthreads();

    int cur = 0;
    for (int s = 0; s < 512; s++) {
        const int u = dir ? (511 - s) : s;
        float nxg0[4] = {0,0,0,0};
        if (s < 511 && isC) {
            int un = dir ? (510 - s) : (s + 1);
#pragma unroll
            for (int g = 0; g < 4; g++) nxg0[g] = XG[xb0 + (size_t)un * 200 + g * 50];
        }
        if (isH) {
#pragma unroll
            for (int r = 0; r < 4; r++) {
                const ulonglong2* hs = (const ulonglong2*)h_sh[cur][r];
                u64 ac0 = 0, ac1 = 0, ac2 = 0, ac3 = 0;
#pragma unroll
                for (int q = 0; q < 12; q++) {
                    ulonglong2 v = hs[q];
                    if (q & 1) { fma2(ac2, v.x, whh2[2 * q]); fma2(ac3, v.y, whh2[2 * q + 1]); }
                    else        { fma2(ac0, v.x, whh2[2 * q]); fma2(ac1, v.y, whh2[2 * q + 1]); }
                }
                {
                    u64 tpair = *(const u64*)&h_sh[cur][r][48];
                    fma2(ac0, tpair, whh2[24]);
                }
                float2 f0 = up2(ac0), f1 = up2(ac1), f2 = up2(ac2), f3 = up2(ac3);
                hg_sh[r][tid] = bias + ((f0.x + f0.y) + (f1.x + f1.y))
                                     + ((f2.x + f2.y) + (f3.x + f3.y));
            }
        }
        __syncthreads();
        if (isC) {
            float gi = xg0[0] + hg_sh[r0][j0];
            float gf = xg0[1] + hg_sh[r0][50 + j0];
            float gg = xg0[2] + hg_sh[r0][100 + j0];
            float go = xg0[3] + hg_sh[r0][150 + j0];
            cc0 = sigm(gf) * cc0 + sigm(gi) * tanh_f(gg);
            float hh = sigm(go) * tanh_f(cc0);
            h_sh[cur ^ 1][r0][j0] = hh;
            int rho = rowBase + r0;
            if (dir == 0) g_F2[((size_t)u * 512 + rho) * 50 + j0] = hh;
            else          g_B2[((size_t)(511 - u) * 512 + rho) * 50 + j0] = hh;
        }
        __syncthreads();
#pragma unroll
        for (int g = 0; g < 4; g++) xg0[g] = nxg0[g];
        cur ^= 1;
    }
}

// ---------------------------------------------------------------------------
// Output linear: out[pos][n] = F2[pos]·wf[n] + B2[pos]·wb[n] + b[n]
// ---------------------------------------------------------------------------
__global__ void __launch_bounds__(256) out_kernel(
    const float* __restrict__ lin_w, const float* __restrict__ lin_b,
    float* __restrict__ out)
{
    __shared__ __align__(16) float wf_sh[45 * 52];
    __shared__ __align__(16) float wb_sh[45 * 52];
    __shared__ float b_sh[45];
    const int tid = threadIdx.x;
    for (int i = tid; i < 45 * 52; i += 256) {
        int n = i / 52, k = i - n * 52;
        wf_sh[i] = (k < 50) ? lin_w[n * 100 + k] : 0.f;
        wb_sh[i] = (k < 50) ? lin_w[n * 100 + 50 + k] : 0.f;
    }
    if (tid < 45) b_sh[tid] = lin_b[tid];
    __syncthreads();

    const int pos = blockIdx.x * 256 + tid;
    float acc[45];
#pragma unroll
    for (int n = 0; n < 45; n++) acc[n] = b_sh[n];

    {
        const float* p = g_F2 + (size_t)pos * 50;
        float xr[50];
#pragma unroll
        for (int k = 0; k < 50; k++) xr[k] = p[k];
        for (int n = 0; n < 45; n++) {
            const float* w = wf_sh + n * 52;
            float a0 = 0.f, a1 = 0.f, a2 = 0.f, a3 = 0.f;
#pragma unroll
            for (int k = 0; k < 48; k += 4) {
                float4 wv = *(const float4*)(w + k);
                a0 += xr[k]     * wv.x;
                a1 += xr[k + 1] * wv.y;
                a2 += xr[k + 2] * wv.z;
                a3 += xr[k + 3] * wv.w;
            }
            a0 += xr[48] * w[48];
            a1 += xr[49] * w[49];
            acc[n] += (a0 + a1) + (a2 + a3);
        }
    }
    {
        const float* p = g_B2 + (size_t)pos * 50;
        float xr[50];
#pragma unroll
        for (int k = 0; k < 50; k++) xr[k] = p[k];
        for (int n = 0; n < 45; n++) {
            const float* w = wb_sh + n * 52;
            float a0 = 0.f, a1 = 0.f, a2 = 0.f, a3 = 0.f;
#pragma unroll
            for (int k = 0; k < 48; k += 4) {
                float4 wv = *(const float4*)(w + k);
                a0 += xr[k]     * wv.x;
                a1 += xr[k + 1] * wv.y;
                a2 += xr[k + 2] * wv.z;
                a3 += xr[k + 3] * wv.w;
            }
            a0 += xr[48] * w[48];
            a1 += xr[49] * w[49];
            acc[n] += (a0 + a1) + (a2 + a3);
        }
    }
    float* o = out + (size_t)pos * 45;
#pragma unroll
    for (int n = 0; n < 45; n++) o[n] = acc[n];
}

// ---------------------------------------------------------------------------
extern "C" void kernel_launch(void* const* d_in, const int* in_sizes, int n_in,
                              void* d_out, int out_size) {
    const int*   x       = (const int*)  d_in[0];
    const float* emb_f1  = (const float*)d_in[1];
    const float* emb_b1  = (const float*)d_in[2];
    const float* h0_f1   = (const float*)d_in[3];
    const float* c0_f1   = (const float*)d_in[4];
    const float* Wih_f1  = (const float*)d_in[5];
    const float* Whh_f1  = (const float*)d_in[6];
    const float* bih_f1  = (const float*)d_in[7];
    const float* bhh_f1  = (const float*)d_in[8];
    const float* h0_b1   = (const float*)d_in[9];
    const float* c0_b1   = (const float*)d_in[10];
    const float* Wih_b1  = (const float*)d_in[11];
    const float* Whh_b1  = (const float*)d_in[12];
    const float* bih_b1  = (const float*)d_in[13];
    const float* bhh_b1  = (const float*)d_in[14];
    const float* h0_f2   = (const float*)d_in[15];
    const float* c0_f2   = (const float*)d_in[16];
    const float* Wih_f2  = (const float*)d_in[17];
    const float* Whh_f2  = (const float*)d_in[18];
    const float* bih_f2  = (const float*)d_in[19];
    const float* bhh_f2  = (const float*)d_in[20];
    const float* h0_b2   = (const float*)d_in[21];
    const float* c0_b2   = (const float*)d_in[22];
    const float* Wih_b2  = (const float*)d_in[23];
    const float* Whh_b2  = (const float*)d_in[24];
    const float* bih_b2  = (const float*)d_in[25];
    const float* bhh_b2  = (const float*)d_in[26];
    const float* lin_w   = (const float*)d_in[27];
    const float* lin_b   = (const float*)d_in[28];
    float* out = (float*)d_out;

    int nvocab = in_sizes[1] / 20;
    if (nvocab > 50000) nvocab = 50000;
    int tg_blocks = (nvocab + 255) / 256;

    detect_kernel<<<1, 1>>>(x);
    convert_kernel<<<1024, 256>>>(x);
    tokgate_kernel<<<tg_blocks, 256>>>(emb_f1, Wih_f1, 0, nvocab);
    tokgate_kernel<<<tg_blocks, 256>>>(emb_b1, Wih_b1, 1, nvocab);
    r1_kernel<<<256, 128>>>(h0_f1, c0_f1, Whh_f1, bih_f1, bhh_f1,
                            h0_b1, c0_b1, Whh_b1, bih_b1, bhh_b1);
    xg2_kernel<<<8192, 256>>>(Wih_f2, Wih_b2);
    r2_kernel<<<256, 224>>>(h0_f2, c0_f2, Whh_f2, bih_f2, bhh_f2,
                            h0_b2, c0_b2, Whh_b2, bih_b2, bhh_b2);
    out_kernel<<<1024, 256>>>(lin_w, lin_b, out);
}

// round 8
// speedup vs baseline: 1.4410x; 1.0021x over previous
#include <cuda_runtime.h>
#include <cuda_bf16.h>

// ---------------------------------------------------------------------------
// Tagger: 2-layer bidirectional LSTM (B=S=512, E=20, H1=30, H2=50, NTAGS=45)
// Reference quirk: (S,B,H)->(B,S,H) reshape with S==B is an index swap.
// Storage convention (all [time][batch][h]):
//   F1[t][b], B1[t][b]  : layer-1 hidden at time t, batch b
//   layer-2 row rho consumes at step u: ( F1[rho][u], B1[511-rho][u] )
//   F2 stored [u][rho]; B2 stored [511-u][rho]  =>  OUT reads both at [i][j].
//
// Non-recurrent work hoisted out of the scans:
//   TG[dir][tok][120]        = Wih1 · emb[tok]
//   XG[dir][rho*512+u][200]  = Wih2 · (F1[rho][u], B1[511-rho][u])
// Scan kernels compute only Whh·h (+bias), fusing prefetched TG/XG in combine.
// Scans use SMALL blocks (4 rows) at 2 blocks/SM so two independent barrier
// domains overlap. xg2 stages its output through shared memory so XG rows are
// written fully coalesced (the naive per-gate-column store was stride-800B).
// ---------------------------------------------------------------------------

typedef unsigned long long u64;

__device__ float g_F1[512 * 512 * 30];
__device__ float g_B1[512 * 512 * 30];
__device__ float g_F2[512 * 512 * 50];
__device__ float g_B2[512 * 512 * 50];
__device__ float g_TGf[50000 * 120];
__device__ float g_TGb[50000 * 120];
__device__ float g_XGf[512 * 512 * 200];
__device__ float g_XGb[512 * 512 * 200];
__device__ int   g_xidx[512 * 512];
__device__ int   g_is64;

__device__ __forceinline__ void fma2(u64 &acc, u64 a, u64 b) {
    asm("fma.rn.f32x2 %0, %1, %2, %0;" : "+l"(acc) : "l"(a), "l"(b));
}
__device__ __forceinline__ float2 up2(u64 v) {
    float2 r; asm("mov.b64 {%0, %1}, %2;" : "=f"(r.x), "=f"(r.y) : "l"(v));
    return r;
}

__device__ __forceinline__ float sigm(float x) {
    return __fdividef(1.f, 1.f + __expf(-x));
}
__device__ __forceinline__ float tanh_f(float x) {
    float a = fabsf(x);
    float e = __expf(-2.f * a);
    float t = __fdividef(1.f - e, 1.f + e);
    return x < 0.f ? -t : t;
}

// x may arrive as int32 (JAX default) or int64 (reference dtype). If int64,
// all odd 32-bit words are zero (tokens < 50000).
__global__ void detect_kernel(const int* __restrict__ xr) {
    int z = 0;
    for (int i = 1; i < 256; i += 2) z |= xr[i];
    g_is64 = (z == 0) ? 1 : 0;
}

__global__ void convert_kernel(const int* __restrict__ xr) {
    int i = blockIdx.x * blockDim.x + threadIdx.x;
    int is64 = g_is64;
    if (i < 512 * 512) g_xidx[i] = is64 ? xr[2 * i] : xr[i];
}

// ---------------------------------------------------------------------------
// Token gate table: TG[tok][j] = Wih1[j] · emb[tok]   (j < 120)
// ---------------------------------------------------------------------------
__global__ void __launch_bounds__(256) tokgate_kernel(
    const float* __restrict__ emb, const float* __restrict__ Wih,
    int dir, int nvocab)
{
    float* TG = dir ? g_TGb : g_TGf;
    __shared__ __align__(16) float e_sh[256][20];
    const int tid = threadIdx.x;
    const int base = blockIdx.x * 256;
    for (int idx = tid; idx < 256 * 20; idx += 256) {
        int tl = idx / 20, k = idx - tl * 20;
        int tok = base + tl;
        e_sh[tl][k] = (tok < nvocab) ? emb[tok * 20 + k] : 0.f;
    }
    __syncthreads();
    if (tid < 120) {
        u64 w2[10];
        const u64* wa = (const u64*)(Wih + tid * 20);
#pragma unroll
        for (int k = 0; k < 10; k++) w2[k] = wa[k];
        int nmax = nvocab - base; if (nmax > 256) nmax = 256;
        for (int tl = 0; tl < nmax; tl++) {
            const ulonglong2* xs = (const ulonglong2*)e_sh[tl];
            u64 ac0 = 0, ac1 = 0, ac2 = 0, ac3 = 0;
#pragma unroll
            for (int q = 0; q < 5; q++) {
                ulonglong2 v = xs[q];
                if (q & 1) { fma2(ac2, v.x, w2[2 * q]); fma2(ac3, v.y, w2[2 * q + 1]); }
                else        { fma2(ac0, v.x, w2[2 * q]); fma2(ac1, v.y, w2[2 * q + 1]); }
            }
            float2 f0 = up2(ac0), f1 = up2(ac1), f2 = up2(ac2), f3 = up2(ac3);
            TG[(base + tl) * 120 + tid] = ((f0.x + f0.y) + (f1.x + f1.y))
                                        + ((f2.x + f2.y) + (f3.x + f3.y));
        }
    }
}

// ---------------------------------------------------------------------------
// Layer-2 input gates: XG[rho*512+u][j] = Wih2[j] · (F1[rho][u], B1[511-rho][u])
// grid = 8192: dir = bx>>12, rho = (bx&4095)>>3, u-chunk = (bx&7)*64
// Output is staged through shared memory in 4 chunks of 16 positions so the
// global stores are fully coalesced 200-float rows.
// ---------------------------------------------------------------------------
__global__ void __launch_bounds__(256) xg2_kernel(
    const float* __restrict__ Wihf, const float* __restrict__ Wihb)
{
    const int bx = blockIdx.x;
    const int dir = bx >> 12;
    const int rem = bx & 4095;
    const int rho = rem >> 3;
    const int u0  = (rem & 7) * 64;
    const float* Wih = dir ? Wihb : Wihf;
    float* XG = dir ? g_XGb : g_XGf;

    __shared__ __align__(16) float x_sh[64][60];
    __shared__ __align__(16) float stage_sh[16][200];
    const int tid = threadIdx.x;
    const float* f1 = g_F1 + ((size_t)rho * 512 + u0) * 30;
    const float* b1 = g_B1 + ((size_t)(511 - rho) * 512 + u0) * 30;
    for (int idx = tid; idx < 1920; idx += 256) {
        int r = idx / 30, k = idx - r * 30;
        x_sh[r][k]      = f1[idx];
        x_sh[r][30 + k] = b1[idx];
    }

    u64 w2[30];
    if (tid < 200) {
        const u64* wa = (const u64*)(Wih + tid * 60);
#pragma unroll
        for (int k = 0; k < 30; k++) w2[k] = wa[k];
    }
    __syncthreads();

    float* outbase = XG + ((size_t)rho * 512 + u0) * 200;
#pragma unroll 1
    for (int c = 0; c < 4; c++) {
        if (tid < 200) {
#pragma unroll 2
            for (int p = 0; p < 16; p++) {
                const ulonglong2* xs = (const ulonglong2*)x_sh[c * 16 + p];
                u64 ac0 = 0, ac1 = 0, ac2 = 0, ac3 = 0;
#pragma unroll
                for (int q = 0; q < 15; q++) {
                    ulonglong2 v = xs[q];
                    if (q & 1) { fma2(ac2, v.x, w2[2 * q]); fma2(ac3, v.y, w2[2 * q + 1]); }
                    else        { fma2(ac0, v.x, w2[2 * q]); fma2(ac1, v.y, w2[2 * q + 1]); }
                }
                float2 f0 = up2(ac0), f1v = up2(ac1), f2 = up2(ac2), f3 = up2(ac3);
                stage_sh[p][tid] = ((f0.x + f0.y) + (f1v.x + f1v.y))
                                 + ((f2.x + f2.y) + (f3.x + f3.y));
            }
        }
        __syncthreads();
        // coalesced store: 16 rows x 200 floats contiguous per row
        float* ob = outbase + (size_t)(c * 16) * 200;
        for (int idx = tid; idx < 3200; idx += 256) {
            ob[idx] = ((const float*)stage_sh)[idx];
        }
        __syncthreads();
    }
}

// ---------------------------------------------------------------------------
// Layer 1 scan: 256 blocks (2 dirs x 128), 4 batch rows/block, 128 threads,
// 2 blocks/SM. Gate threads tid<120 compute ONLY Whh·h + bias.
// Combine: 120 tasks, exactly 1/thread, fusing prefetched TG.
// ---------------------------------------------------------------------------
__global__ void __launch_bounds__(128, 2) r1_kernel(
    const float* __restrict__ h0f, const float* __restrict__ c0f,
    const float* __restrict__ Whhf,
    const float* __restrict__ bihf, const float* __restrict__ bhhf,
    const float* __restrict__ h0b, const float* __restrict__ c0b,
    const float* __restrict__ Whhb,
    const float* __restrict__ bihb, const float* __restrict__ bhhb)
{
    const int dir = blockIdx.x >> 7;           // 0 = forward, 1 = backward
    const int rowBase = (blockIdx.x & 127) * 4;
    const float* Whh = dir ? Whhb : Whhf;
    const float* bih = dir ? bihb : bihf;
    const float* bhh = dir ? bhhb : bhhf;
    const float* h0  = dir ? h0b  : h0f;
    const float* c0  = dir ? c0b  : c0f;
    const float* TG  = dir ? g_TGb : g_TGf;
    float* outp = dir ? g_B1 : g_F1;

    const int tid = threadIdx.x;
    __shared__ __align__(16) float h_sh[2][4][32];
    __shared__ float hg_sh[4][120];

    const bool isH = (tid < 120);
    u64 whh2[15];
    float bias = 0.f;
    if (isH) {
        const u64* wb = (const u64*)(Whh + tid * 30);   // 120B rows, 8B-aligned
#pragma unroll
        for (int k = 0; k < 15; k++) whh2[k] = wb[k];
        bias = bih[tid] + bhh[tid];
    }
    for (int idx = tid; idx < 4 * 32; idx += 128) {
        int r = idx >> 5, k = idx & 31;
        h_sh[0][r][k] = (k < 30) ? h0[(rowBase + r) * 30 + k] : 0.f;
        h_sh[1][r][k] = 0.f;
    }
    // combine: task m = tid in [0,120): r = m/30, j = m%30
    const int r0 = tid / 30, j0 = tid - r0 * 30;
    const bool isC = (tid < 120);
    float cc0 = isC ? c0[(rowBase + r0) * 30 + j0] : 0.f;

    // prefetch token gates for step 0
    float tg0[4] = {0,0,0,0};
    if (isC) {
        int t0 = dir ? 511 : 0;
        int tok = g_xidx[(rowBase + r0) * 512 + t0];
#pragma unroll
        for (int g = 0; g < 4; g++) tg0[g] = TG[tok * 120 + g * 30 + j0];
    }
    __syncthreads();

    int cur = 0;
    for (int s = 0; s < 512; s++) {
        const int t = dir ? (511 - s) : s;
        // prefetch next step's token gates (hidden under gate FMA stretch)
        float ntg0[4] = {0,0,0,0};
        if (s < 511 && isC) {
            int tn = dir ? (510 - s) : (s + 1);
            int tok = g_xidx[(rowBase + r0) * 512 + tn];
#pragma unroll
            for (int g = 0; g < 4; g++) ntg0[g] = TG[tok * 120 + g * 30 + j0];
        }
        if (isH) {
#pragma unroll
            for (int r = 0; r < 4; r++) {
                const ulonglong2* hs = (const ulonglong2*)h_sh[cur][r];
                u64 ac0 = 0, ac1 = 0, ac2 = 0, ac3 = 0;
#pragma unroll
                for (int q = 0; q < 7; q++) {
                    ulonglong2 v = hs[q];
                    if (q & 1) { fma2(ac2, v.x, whh2[2 * q]); fma2(ac3, v.y, whh2[2 * q + 1]); }
                    else        { fma2(ac0, v.x, whh2[2 * q]); fma2(ac1, v.y, whh2[2 * q + 1]); }
                }
                {
                    u64 tpair = *(const u64*)&h_sh[cur][r][28];
                    fma2(ac2, tpair, whh2[14]);
                }
                float2 f0 = up2(ac0), f1 = up2(ac1), f2 = up2(ac2), f3 = up2(ac3);
                hg_sh[r][tid] = bias + ((f0.x + f0.y) + (f1.x + f1.y))
                                     + ((f2.x + f2.y) + (f3.x + f3.y));
            }
        }
        __syncthreads();
        if (isC) {
            float gi = tg0[0] + hg_sh[r0][j0];
            float gf = tg0[1] + hg_sh[r0][30 + j0];
            float gg = tg0[2] + hg_sh[r0][60 + j0];
            float go = tg0[3] + hg_sh[r0][90 + j0];
            cc0 = sigm(gf) * cc0 + sigm(gi) * tanh_f(gg);
            float hh = sigm(go) * tanh_f(cc0);
            h_sh[cur ^ 1][r0][j0] = hh;
            outp[((size_t)t * 512 + (rowBase + r0)) * 30 + j0] = hh;
        }
        __syncthreads();
#pragma unroll
        for (int g = 0; g < 4; g++) tg0[g] = ntg0[g];
        cur ^= 1;
    }
}

// ---------------------------------------------------------------------------
// Layer 2 scan: 256 blocks (2 dirs x 128), 4 rho-rows/block, 224 threads,
// 2 blocks/SM. Gate threads tid<200 compute ONLY Whh·h + bias.
// Combine: 200 tasks, exactly 1/thread, fusing prefetched XG.
// ---------------------------------------------------------------------------
__global__ void __launch_bounds__(224, 2) r2_kernel(
    const float* __restrict__ h0f, const float* __restrict__ c0f,
    const float* __restrict__ Whhf,
    const float* __restrict__ bihf, const float* __restrict__ bhhf,
    const float* __restrict__ h0b, const float* __restrict__ c0b,
    const float* __restrict__ Whhb,
    const float* __restrict__ bihb, const float* __restrict__ bhhb)
{
    const int dir = blockIdx.x >> 7;
    const int rowBase = (blockIdx.x & 127) * 4;
    const float* Whh = dir ? Whhb : Whhf;
    const float* bih = dir ? bihb : bihf;
    const float* bhh = dir ? bhhb : bhhf;
    const float* h0  = dir ? h0b  : h0f;
    const float* c0  = dir ? c0b  : c0f;
    const float* XG  = dir ? g_XGb : g_XGf;

    const int tid = threadIdx.x;
    __shared__ __align__(16) float h_sh[2][4][52];
    __shared__ float hg_sh[4][200];

    const bool isH = (tid < 200);
    u64 whh2[25];
    float bias = 0.f;
    if (isH) {
        const u64* wb = (const u64*)(Whh + tid * 50);   // 200B rows, 8B-aligned
#pragma unroll
        for (int k = 0; k < 25; k++) whh2[k] = wb[k];
        bias = bih[tid] + bhh[tid];
    }
    for (int idx = tid; idx < 4 * 52; idx += 224) {
        int r = idx / 52, k = idx - r * 52;
        h_sh[0][r][k] = (k < 50) ? h0[(rowBase + r) * 50 + k] : 0.f;
        h_sh[1][r][k] = 0.f;
    }
    // combine: task m = tid in [0,200): r = m/50, j = m%50
    const int r0 = tid / 50, j0 = tid - r0 * 50;
    const bool isC = (tid < 200);
    float cc0 = isC ? c0[(rowBase + r0) * 50 + j0] : 0.f;
    const size_t xb0 = ((size_t)(rowBase + r0) * 512) * 200 + j0;

    // prefetch XG for step 0
    float xg0[4] = {0,0,0,0};
    if (isC) {
        int u0 = dir ? 511 : 0;
#pragma unroll
        for (int g = 0; g < 4; g++) xg0[g] = XG[xb0 + (size_t)u0 * 200 + g * 50];
    }
    __syncthreads();

    int cur = 0;
    for (int s = 0; s < 512; s++) {
        const int u = dir ? (511 - s) : s;
        float nxg0[4] = {0,0,0,0};
        if (s < 511 && isC) {
            int un = dir ? (510 - s) : (s + 1);
#pragma unroll
            for (int g = 0; g < 4; g++) nxg0[g] = XG[xb0 + (size_t)un * 200 + g * 50];
        }
        if (isH) {
#pragma unroll
            for (int r = 0; r < 4; r++) {
                const ulonglong2* hs = (const ulonglong2*)h_sh[cur][r];
                u64 ac0 = 0, ac1 = 0, ac2 = 0, ac3 = 0;
#pragma unroll
                for (int q = 0; q < 12; q++) {
                    ulonglong2 v = hs[q];
                    if (q & 1) { fma2(ac2, v.x, whh2[2 * q]); fma2(ac3, v.y, whh2[2 * q + 1]); }
                    else        { fma2(ac0, v.x, whh2[2 * q]); fma2(ac1, v.y, whh2[2 * q + 1]); }
                }
                {
                    u64 tpair = *(const u64*)&h_sh[cur][r][48];
                    fma2(ac0, tpair, whh2[24]);
                }
                float2 f0 = up2(ac0), f1 = up2(ac1), f2 = up2(ac2), f3 = up2(ac3);
                hg_sh[r][tid] = bias + ((f0.x + f0.y) + (f1.x + f1.y))
                                     + ((f2.x + f2.y) + (f3.x + f3.y));
            }
        }
        __syncthreads();
        if (isC) {
            float gi = xg0[0] + hg_sh[r0][j0];
            float gf = xg0[1] + hg_sh[r0][50 + j0];
            float gg = xg0[2] + hg_sh[r0][100 + j0];
            float go = xg0[3] + hg_sh[r0][150 + j0];
            cc0 = sigm(gf) * cc0 + sigm(gi) * tanh_f(gg);
            float hh = sigm(go) * tanh_f(cc0);
            h_sh[cur ^ 1][r0][j0] = hh;
            int rho = rowBase + r0;
            if (dir == 0) g_F2[((size_t)u * 512 + rho) * 50 + j0] = hh;
            else          g_B2[((size_t)(511 - u) * 512 + rho) * 50 + j0] = hh;
        }
        __syncthreads();
#pragma unroll
        for (int g = 0; g < 4; g++) xg0[g] = nxg0[g];
        cur ^= 1;
    }
}

// ---------------------------------------------------------------------------
// Output linear: out[pos][n] = F2[pos]·wf[n] + B2[pos]·wb[n] + b[n]
// ---------------------------------------------------------------------------
__global__ void __launch_bounds__(256) out_kernel(
    const float* __restrict__ lin_w, const float* __restrict__ lin_b,
    float* __restrict__ out)
{
    __shared__ __align__(16) float wf_sh[45 * 52];
    __shared__ __align__(16) float wb_sh[45 * 52];
    __shared__ float b_sh[45];
    const int tid = threadIdx.x;
    for (int i = tid; i < 45 * 52; i += 256) {
        int n = i / 52, k = i - n * 52;
        wf_sh[i] = (k < 50) ? lin_w[n * 100 + k] : 0.f;
        wb_sh[i] = (k < 50) ? lin_w[n * 100 + 50 + k] : 0.f;
    }
    if (tid < 45) b_sh[tid] = lin_b[tid];
    __syncthreads();

    const int pos = blockIdx.x * 256 + tid;
    float acc[45];
#pragma unroll
    for (int n = 0; n < 45; n++) acc[n] = b_sh[n];

    {
        const float* p = g_F2 + (size_t)pos * 50;
        float xr[50];
#pragma unroll
        for (int k = 0; k < 50; k++) xr[k] = p[k];
        for (int n = 0; n < 45; n++) {
            const float* w = wf_sh + n * 52;
            float a0 = 0.f, a1 = 0.f, a2 = 0.f, a3 = 0.f;
#pragma unroll
            for (int k = 0; k < 48; k += 4) {
                float4 wv = *(const float4*)(w + k);
                a0 += xr[k]     * wv.x;
                a1 += xr[k + 1] * wv.y;
                a2 += xr[k + 2] * wv.z;
                a3 += xr[k + 3] * wv.w;
            }
            a0 += xr[48] * w[48];
            a1 += xr[49] * w[49];
            acc[n] += (a0 + a1) + (a2 + a3);
        }
    }
    {
        const float* p = g_B2 + (size_t)pos * 50;
        float xr[50];
#pragma unroll
        for (int k = 0; k < 50; k++) xr[k] = p[k];
        for (int n = 0; n < 45; n++) {
            const float* w = wb_sh + n * 52;
            float a0 = 0.f, a1 = 0.f, a2 = 0.f, a3 = 0.f;
#pragma unroll
            for (int k = 0; k < 48; k += 4) {
                float4 wv = *(const float4*)(w + k);
                a0 += xr[k]     * wv.x;
                a1 += xr[k + 1] * wv.y;
                a2 += xr[k + 2] * wv.z;
                a3 += xr[k + 3] * wv.w;
            }
            a0 += xr[48] * w[48];
            a1 += xr[49] * w[49];
            acc[n] += (a0 + a1) + (a2 + a3);
        }
    }
    float* o = out + (size_t)pos * 45;
#pragma unroll
    for (int n = 0; n < 45; n++) o[n] = acc[n];
}

// ---------------------------------------------------------------------------
extern "C" void kernel_launch(void* const* d_in, const int* in_sizes, int n_in,
                              void* d_out, int out_size) {
    const int*   x       = (const int*)  d_in[0];
    const float* emb_f1  = (const float*)d_in[1];
    const float* emb_b1  = (const float*)d_in[2];
    const float* h0_f1   = (const float*)d_in[3];
    const float* c0_f1   = (const float*)d_in[4];
    const float* Wih_f1  = (const float*)d_in[5];
    const float* Whh_f1  = (const float*)d_in[6];
    const float* bih_f1  = (const float*)d_in[7];
    const float* bhh_f1  = (const float*)d_in[8];
    const float* h0_b1   = (const float*)d_in[9];
    const float* c0_b1   = (const float*)d_in[10];
    const float* Wih_b1  = (const float*)d_in[11];
    const float* Whh_b1  = (const float*)d_in[12];
    const float* bih_b1  = (const float*)d_in[13];
    const float* bhh_b1  = (const float*)d_in[14];
    const float* h0_f2   = (const float*)d_in[15];
    const float* c0_f2   = (const float*)d_in[16];
    const float* Wih_f2  = (const float*)d_in[17];
    const float* Whh_f2  = (const float*)d_in[18];
    const float* bih_f2  = (const float*)d_in[19];
    const float* bhh_f2  = (const float*)d_in[20];
    const float* h0_b2   = (const float*)d_in[21];
    const float* c0_b2   = (const float*)d_in[22];
    const float* Wih_b2  = (const float*)d_in[23];
    const float* Whh_b2  = (const float*)d_in[24];
    const float* bih_b2  = (const float*)d_in[25];
    const float* bhh_b2  = (const float*)d_in[26];
    const float* lin_w   = (const float*)d_in[27];
    const float* lin_b   = (const float*)d_in[28];
    float* out = (float*)d_out;

    int nvocab = in_sizes[1] / 20;
    if (nvocab > 50000) nvocab = 50000;
    int tg_blocks = (nvocab + 255) / 256;

    detect_kernel<<<1, 1>>>(x);
    convert_kernel<<<1024, 256>>>(x);
    tokgate_kernel<<<tg_blocks, 256>>>(emb_f1, Wih_f1, 0, nvocab);
    tokgate_kernel<<<tg_blocks, 256>>>(emb_b1, Wih_b1, 1, nvocab);
    r1_kernel<<<256, 128>>>(h0_f1, c0_f1, Whh_f1, bih_f1, bhh_f1,
                            h0_b1, c0_b1, Whh_b1, bih_b1, bhh_b1);
    xg2_kernel<<<8192, 256>>>(Wih_f2, Wih_b2);
    r2_kernel<<<256, 224>>>(h0_f2, c0_f2, Whh_f2, bih_f2, bhh_f2,
                            h0_b2, c0_b2, Whh_b2, bih_b2, bhh_b2);
    out_kernel<<<1024, 256>>>(lin_w, lin_b, out);
}

// round 9
// speedup vs baseline: 1.4614x; 1.0141x over previous
#include <cuda_runtime.h>
#include <cuda_bf16.h>

// ---------------------------------------------------------------------------
// Tagger: 2-layer bidirectional LSTM (B=S=512, E=20, H1=30, H2=50, NTAGS=45)
// Reference quirk: (S,B,H)->(B,S,H) reshape with S==B is an index swap.
// Storage convention (all [time][batch][h]):
//   F1[t][b], B1[t][b]  : layer-1 hidden at time t, batch b
//   layer-2 row rho consumes at step u: ( F1[rho][u], B1[511-rho][u] )
//   F2 stored [u][rho]; B2 stored [511-u][rho]  =>  OUT reads both at [i][j].
//
// Non-recurrent work hoisted out of the scans:
//   TG[dir][tok][120]        = Wih1 · emb[tok]
//   XG[dir][rho*512+u][200]  = Wih2 · (F1[rho][u], B1[511-rho][u])
// Scan kernels compute only Whh·h (+bias), fusing prefetched TG/XG in combine.
// Scans use SMALL blocks (r1: 2 rows @ 4/SM, r2: 3 rows @ 3/SM) so multiple
// independent barrier domains overlap per SM.
// ---------------------------------------------------------------------------

typedef unsigned long long u64;

__device__ float g_F1[512 * 512 * 30];
__device__ float g_B1[512 * 512 * 30];
__device__ float g_F2[512 * 512 * 50];
__device__ float g_B2[512 * 512 * 50];
__device__ float g_TGf[50000 * 120];
__device__ float g_TGb[50000 * 120];
__device__ float g_XGf[512 * 512 * 200];
__device__ float g_XGb[512 * 512 * 200];
__device__ int   g_xidx[512 * 512];
__device__ int   g_is64;

__device__ __forceinline__ void fma2(u64 &acc, u64 a, u64 b) {
    asm("fma.rn.f32x2 %0, %1, %2, %0;" : "+l"(acc) : "l"(a), "l"(b));
}
__device__ __forceinline__ float2 up2(u64 v) {
    float2 r; asm("mov.b64 {%0, %1}, %2;" : "=f"(r.x), "=f"(r.y) : "l"(v));
    return r;
}

__device__ __forceinline__ float sigm(float x) {
    return __fdividef(1.f, 1.f + __expf(-x));
}
__device__ __forceinline__ float tanh_f(float x) {
    float a = fabsf(x);
    float e = __expf(-2.f * a);
    float t = __fdividef(1.f - e, 1.f + e);
    return x < 0.f ? -t : t;
}

// x may arrive as int32 (JAX default) or int64 (reference dtype). If int64,
// all odd 32-bit words are zero (tokens < 50000).
__global__ void detect_kernel(const int* __restrict__ xr) {
    int z = 0;
    for (int i = 1; i < 256; i += 2) z |= xr[i];
    g_is64 = (z == 0) ? 1 : 0;
}

__global__ void convert_kernel(const int* __restrict__ xr) {
    int i = blockIdx.x * blockDim.x + threadIdx.x;
    int is64 = g_is64;
    if (i < 512 * 512) g_xidx[i] = is64 ? xr[2 * i] : xr[i];
}

// ---------------------------------------------------------------------------
// Token gate table, BOTH dirs in one launch:
//   TG[dir][tok][j] = Wih1[dir][j] · emb[dir][tok]   (j < 120)
// grid = 2 * tg_blocks; dir = bx >= tg_blocks
// ---------------------------------------------------------------------------
__global__ void __launch_bounds__(256) tokgate_kernel(
    const float* __restrict__ emb_f, const float* __restrict__ Wih_f,
    const float* __restrict__ emb_b, const float* __restrict__ Wih_b,
    int tg_blocks, int nvocab)
{
    const int dir = (blockIdx.x >= tg_blocks) ? 1 : 0;
    const float* emb = dir ? emb_b : emb_f;
    const float* Wih = dir ? Wih_b : Wih_f;
    float* TG = dir ? g_TGb : g_TGf;

    __shared__ __align__(16) float e_sh[256][20];
    const int tid = threadIdx.x;
    const int base = (blockIdx.x - dir * tg_blocks) * 256;
    for (int idx = tid; idx < 256 * 20; idx += 256) {
        int tl = idx / 20, k = idx - tl * 20;
        int tok = base + tl;
        e_sh[tl][k] = (tok < nvocab) ? emb[tok * 20 + k] : 0.f;
    }
    __syncthreads();
    if (tid < 120) {
        u64 w2[10];
        const u64* wa = (const u64*)(Wih + tid * 20);
#pragma unroll
        for (int k = 0; k < 10; k++) w2[k] = wa[k];
        int nmax = nvocab - base; if (nmax > 256) nmax = 256;
        for (int tl = 0; tl < nmax; tl++) {
            const ulonglong2* xs = (const ulonglong2*)e_sh[tl];
            u64 ac0 = 0, ac1 = 0, ac2 = 0, ac3 = 0;
#pragma unroll
            for (int q = 0; q < 5; q++) {
                ulonglong2 v = xs[q];
                if (q & 1) { fma2(ac2, v.x, w2[2 * q]); fma2(ac3, v.y, w2[2 * q + 1]); }
                else        { fma2(ac0, v.x, w2[2 * q]); fma2(ac1, v.y, w2[2 * q + 1]); }
            }
            float2 f0 = up2(ac0), f1 = up2(ac1), f2 = up2(ac2), f3 = up2(ac3);
            TG[(base + tl) * 120 + tid] = ((f0.x + f0.y) + (f1.x + f1.y))
                                        + ((f2.x + f2.y) + (f3.x + f3.y));
        }
    }
}

// ---------------------------------------------------------------------------
// Layer 1 scan: 512 blocks (2 dirs x 256), 2 batch rows/block, 128 threads,
// 4 blocks/SM. Gate threads tid<120 compute ONLY Whh·h + bias (2 rows).
// Combine: 60 tasks (tid<60), fusing prefetched TG.
// ---------------------------------------------------------------------------
__global__ void __launch_bounds__(128, 4) r1_kernel(
    const float* __restrict__ h0f, const float* __restrict__ c0f,
    const float* __restrict__ Whhf,
    const float* __restrict__ bihf, const float* __restrict__ bhhf,
    const float* __restrict__ h0b, const float* __restrict__ c0b,
    const float* __restrict__ Whhb,
    const float* __restrict__ bihb, const float* __restrict__ bhhb)
{
    const int dir = blockIdx.x >> 8;           // 0 = forward, 1 = backward
    const int rowBase = (blockIdx.x & 255) * 2;
    const float* Whh = dir ? Whhb : Whhf;
    const float* bih = dir ? bihb : bihf;
    const float* bhh = dir ? bhhb : bhhf;
    const float* h0  = dir ? h0b  : h0f;
    const float* c0  = dir ? c0b  : c0f;
    const float* TG  = dir ? g_TGb : g_TGf;
    float* outp = dir ? g_B1 : g_F1;

    const int tid = threadIdx.x;
    __shared__ __align__(16) float h_sh[2][2][32];
    __shared__ float hg_sh[2][120];

    const bool isH = (tid < 120);
    u64 whh2[15];
    float bias = 0.f;
    if (isH) {
        const u64* wb = (const u64*)(Whh + tid * 30);   // 120B rows, 8B-aligned
#pragma unroll
        for (int k = 0; k < 15; k++) whh2[k] = wb[k];
        bias = bih[tid] + bhh[tid];
    }
    for (int idx = tid; idx < 2 * 32; idx += 128) {
        int r = idx >> 5, k = idx & 31;
        h_sh[0][r][k] = (k < 30) ? h0[(rowBase + r) * 30 + k] : 0.f;
        h_sh[1][r][k] = 0.f;
    }
    // combine: task m = tid in [0,60): r = m/30, j = m%30
    const int r0 = tid / 30, j0 = tid - r0 * 30;
    const bool isC = (tid < 60);
    float cc0 = isC ? c0[(rowBase + r0) * 30 + j0] : 0.f;

    // prefetch token gates for step 0
    float tg0[4] = {0,0,0,0};
    if (isC) {
        int t0 = dir ? 511 : 0;
        int tok = g_xidx[(rowBase + r0) * 512 + t0];
#pragma unroll
        for (int g = 0; g < 4; g++) tg0[g] = TG[tok * 120 + g * 30 + j0];
    }
    __syncthreads();

    int cur = 0;
    for (int s = 0; s < 512; s++) {
        const int t = dir ? (511 - s) : s;
        // prefetch next step's token gates (hidden under gate FMA stretch)
        float ntg0[4] = {0,0,0,0};
        if (s < 511 && isC) {
            int tn = dir ? (510 - s) : (s + 1);
            int tok = g_xidx[(rowBase + r0) * 512 + tn];
#pragma unroll
            for (int g = 0; g < 4; g++) ntg0[g] = TG[tok * 120 + g * 30 + j0];
        }
        if (isH) {
#pragma unroll
            for (int r = 0; r < 2; r++) {
                const ulonglong2* hs = (const ulonglong2*)h_sh[cur][r];
                u64 ac0 = 0, ac1 = 0, ac2 = 0, ac3 = 0;
#pragma unroll
                for (int q = 0; q < 7; q++) {
                    ulonglong2 v = hs[q];
                    if (q & 1) { fma2(ac2, v.x, whh2[2 * q]); fma2(ac3, v.y, whh2[2 * q + 1]); }
                    else        { fma2(ac0, v.x, whh2[2 * q]); fma2(ac1, v.y, whh2[2 * q + 1]); }
                }
                {
                    u64 tpair = *(const u64*)&h_sh[cur][r][28];
                    fma2(ac2, tpair, whh2[14]);
                }
                float2 f0 = up2(ac0), f1 = up2(ac1), f2 = up2(ac2), f3 = up2(ac3);
                hg_sh[r][tid] = bias + ((f0.x + f0.y) + (f1.x + f1.y))
                                     + ((f2.x + f2.y) + (f3.x + f3.y));
            }
        }
        __syncthreads();
        if (isC) {
            float gi = tg0[0] + hg_sh[r0][j0];
            float gf = tg0[1] + hg_sh[r0][30 + j0];
            float gg = tg0[2] + hg_sh[r0][60 + j0];
            float go = tg0[3] + hg_sh[r0][90 + j0];
            cc0 = sigm(gf) * cc0 + sigm(gi) * tanh_f(gg);
            float hh = sigm(go) * tanh_f(cc0);
            h_sh[cur ^ 1][r0][j0] = hh;
            outp[((size_t)t * 512 + (rowBase + r0)) * 30 + j0] = hh;
        }
        __syncthreads();
#pragma unroll
        for (int g = 0; g < 4; g++) tg0[g] = ntg0[g];
        cur ^= 1;
    }
}

// ---------------------------------------------------------------------------
// Layer-2 input gates: XG[rho*512+u][j] = Wih2[j] · (F1[rho][u], B1[511-rho][u])
// grid = 8192: dir = bx>>12, rho = (bx&4095)>>3, u-chunk = (bx&7)*64
// Output staged through shared so XG rows are written fully coalesced.
// ---------------------------------------------------------------------------
__global__ void __launch_bounds__(256) xg2_kernel(
    const float* __restrict__ Wihf, const float* __restrict__ Wihb)
{
    const int bx = blockIdx.x;
    const int dir = bx >> 12;
    const int rem = bx & 4095;
    const int rho = rem >> 3;
    const int u0  = (rem & 7) * 64;
    const float* Wih = dir ? Wihb : Wihf;
    float* XG = dir ? g_XGb : g_XGf;

    __shared__ __align__(16) float x_sh[64][60];
    __shared__ __align__(16) float stage_sh[16][200];
    const int tid = threadIdx.x;
    const float* f1 = g_F1 + ((size_t)rho * 512 + u0) * 30;
    const float* b1 = g_B1 + ((size_t)(511 - rho) * 512 + u0) * 30;
    for (int idx = tid; idx < 1920; idx += 256) {
        int r = idx / 30, k = idx - r * 30;
        x_sh[r][k]      = f1[idx];
        x_sh[r][30 + k] = b1[idx];
    }

    u64 w2[30];
    if (tid < 200) {
        const u64* wa = (const u64*)(Wih + tid * 60);
#pragma unroll
        for (int k = 0; k < 30; k++) w2[k] = wa[k];
    }
    __syncthreads();

    float* outbase = XG + ((size_t)rho * 512 + u0) * 200;
#pragma unroll 1
    for (int c = 0; c < 4; c++) {
        if (tid < 200) {
#pragma unroll 2
            for (int p = 0; p < 16; p++) {
                const ulonglong2* xs = (const ulonglong2*)x_sh[c * 16 + p];
                u64 ac0 = 0, ac1 = 0, ac2 = 0, ac3 = 0;
#pragma unroll
                for (int q = 0; q < 15; q++) {
                    ulonglong2 v = xs[q];
                    if (q & 1) { fma2(ac2, v.x, w2[2 * q]); fma2(ac3, v.y, w2[2 * q + 1]); }
                    else        { fma2(ac0, v.x, w2[2 * q]); fma2(ac1, v.y, w2[2 * q + 1]); }
                }
                float2 f0 = up2(ac0), f1v = up2(ac1), f2 = up2(ac2), f3 = up2(ac3);
                stage_sh[p][tid] = ((f0.x + f0.y) + (f1v.x + f1v.y))
                                 + ((f2.x + f2.y) + (f3.x + f3.y));
            }
        }
        __syncthreads();
        float* ob = outbase + (size_t)(c * 16) * 200;
        for (int idx = tid; idx < 3200; idx += 256) {
            ob[idx] = ((const float*)stage_sh)[idx];
        }
        __syncthreads();
    }
}

// ---------------------------------------------------------------------------
// Layer 2 scan: 342 blocks (2 dirs x 171), 3 rho-rows/block (last block of
// each dir has 2), 224 threads, 3 blocks/SM. Gate threads tid<200 compute
// ONLY Whh·h + bias. Combine: 150 tasks (tid<150), fusing prefetched XG.
// ---------------------------------------------------------------------------
__global__ void __launch_bounds__(224, 3) r2_kernel(
    const float* __restrict__ h0f, const float* __restrict__ c0f,
    const float* __restrict__ Whhf,
    const float* __restrict__ bihf, const float* __restrict__ bhhf,
    const float* __restrict__ h0b, const float* __restrict__ c0b,
    const float* __restrict__ Whhb,
    const float* __restrict__ bihb, const float* __restrict__ bhhb)
{
    const int dir = (blockIdx.x >= 171) ? 1 : 0;
    const int rowBase = (blockIdx.x - dir * 171) * 3;
    const int nrows = (512 - rowBase) < 3 ? (512 - rowBase) : 3;
    const float* Whh = dir ? Whhb : Whhf;
    const float* bih = dir ? bihb : bihf;
    const float* bhh = dir ? bhhb : bhhf;
    const float* h0  = dir ? h0b  : h0f;
    const float* c0  = dir ? c0b  : c0f;
    const float* XG  = dir ? g_XGb : g_XGf;

    const int tid = threadIdx.x;
    __shared__ __align__(16) float h_sh[2][3][52];
    __shared__ float hg_sh[3][200];

    const bool isH = (tid < 200);
    u64 whh2[25];
    float bias = 0.f;
    if (isH) {
        const u64* wb = (const u64*)(Whh + tid * 50);   // 200B rows, 8B-aligned
#pragma unroll
        for (int k = 0; k < 25; k++) whh2[k] = wb[k];
        bias = bih[tid] + bhh[tid];
    }
    for (int idx = tid; idx < 3 * 52; idx += 224) {
        int r = idx / 52, k = idx - r * 52;
        h_sh[0][r][k] = (r < nrows && k < 50) ? h0[(rowBase + r) * 50 + k] : 0.f;
        h_sh[1][r][k] = 0.f;
    }
    // combine: task m = tid in [0,150): r = m/50, j = m%50
    const int r0 = tid / 50, j0 = tid - r0 * 50;
    const bool isC = (tid < 150) && (r0 < nrows);
    float cc0 = isC ? c0[(rowBase + r0) * 50 + j0] : 0.f;
    const size_t xb0 = isC ? ((size_t)(rowBase + r0) * 512) * 200 + j0 : 0;

    // prefetch XG for step 0
    float xg0[4] = {0,0,0,0};
    if (isC) {
        int u0 = dir ? 511 : 0;
#pragma unroll
        for (int g = 0; g < 4; g++) xg0[g] = XG[xb0 + (size_t)u0 * 200 + g * 50];
    }
    __syncthreads();

    int cur = 0;
    for (int s = 0; s < 512; s++) {
        const int u = dir ? (511 - s) : s;
        float nxg0[4] = {0,0,0,0};
        if (s < 511 && isC) {
            int un = dir ? (510 - s) : (s + 1);
#pragma unroll
            for (int g = 0; g < 4; g++) nxg0[g] = XG[xb0 + (size_t)un * 200 + g * 50];
        }
        if (isH) {
#pragma unroll
            for (int r = 0; r < 3; r++) {
                if (r < nrows) {
                    const ulonglong2* hs = (const ulonglong2*)h_sh[cur][r];
                    u64 ac0 = 0, ac1 = 0, ac2 = 0, ac3 = 0;
#pragma unroll
                    for (int q = 0; q < 12; q++) {
                        ulonglong2 v = hs[q];
                        if (q & 1) { fma2(ac2, v.x, whh2[2 * q]); fma2(ac3, v.y, whh2[2 * q + 1]); }
                        else        { fma2(ac0, v.x, whh2[2 * q]); fma2(ac1, v.y, whh2[2 * q + 1]); }
                    }
                    {
                        u64 tpair = *(const u64*)&h_sh[cur][r][48];
                        fma2(ac0, tpair, whh2[24]);
                    }
                    float2 f0 = up2(ac0), f1 = up2(ac1), f2 = up2(ac2), f3 = up2(ac3);
                    hg_sh[r][tid] = bias + ((f0.x + f0.y) + (f1.x + f1.y))
                                         + ((f2.x + f2.y) + (f3.x + f3.y));
                }
            }
        }
        __syncthreads();
        if (isC) {
            float gi = xg0[0] + hg_sh[r0][j0];
            float gf = xg0[1] + hg_sh[r0][50 + j0];
            float gg = xg0[2] + hg_sh[r0][100 + j0];
            float go = xg0[3] + hg_sh[r0][150 + j0];
            cc0 = sigm(gf) * cc0 + sigm(gi) * tanh_f(gg);
            float hh = sigm(go) * tanh_f(cc0);
            h_sh[cur ^ 1][r0][j0] = hh;
            int rho = rowBase + r0;
            if (dir == 0) g_F2[((size_t)u * 512 + rho) * 50 + j0] = hh;
            else          g_B2[((size_t)(511 - u) * 512 + rho) * 50 + j0] = hh;
        }
        __syncthreads();
#pragma unroll
        for (int g = 0; g < 4; g++) xg0[g] = nxg0[g];
        cur ^= 1;
    }
}

// ---------------------------------------------------------------------------
// Output linear (FFMA2): out[pos][n] = F2[pos]·wf[n] + B2[pos]·wb[n] + b[n]
// ---------------------------------------------------------------------------
__global__ void __launch_bounds__(256) out_kernel(
    const float* __restrict__ lin_w, const float* __restrict__ lin_b,
    float* __restrict__ out)
{
    __shared__ __align__(16) float wf_sh[45 * 52];
    __shared__ __align__(16) float wb_sh[45 * 52];
    __shared__ float b_sh[45];
    const int tid = threadIdx.x;
    for (int i = tid; i < 45 * 52; i += 256) {
        int n = i / 52, k = i - n * 52;
        wf_sh[i] = (k < 50) ? lin_w[n * 100 + k] : 0.f;
        wb_sh[i] = (k < 50) ? lin_w[n * 100 + 50 + k] : 0.f;
    }
    if (tid < 45) b_sh[tid] = lin_b[tid];
    __syncthreads();

    const int pos = blockIdx.x * 256 + tid;
    float acc[45];
#pragma unroll
    for (int n = 0; n < 45; n++) acc[n] = b_sh[n];

    {
        const u64* xp = (const u64*)(g_F2 + (size_t)pos * 50);
        u64 xr2[25];
#pragma unroll
        for (int k = 0; k < 25; k++) xr2[k] = xp[k];
#pragma unroll 3
        for (int n = 0; n < 45; n++) {
            const float* w = wf_sh + n * 52;
            const ulonglong2* wv = (const ulonglong2*)w;
            u64 a = 0, b = 0;
#pragma unroll
            for (int q = 0; q < 12; q++) {
                ulonglong2 v = wv[q];
                fma2(a, xr2[2 * q], v.x);
                fma2(b, xr2[2 * q + 1], v.y);
            }
            fma2(a, xr2[24], ((const u64*)w)[24]);
            float2 fa = up2(a), fb = up2(b);
            acc[n] += (fa.x + fa.y) + (fb.x + fb.y);
        }
    }
    {
        const u64* xp = (const u64*)(g_B2 + (size_t)pos * 50);
        u64 xr2[25];
#pragma unroll
        for (int k = 0; k < 25; k++) xr2[k] = xp[k];
#pragma unroll 3
        for (int n = 0; n < 45; n++) {
            const float* w = wb_sh + n * 52;
            const ulonglong2* wv = (const ulonglong2*)w;
            u64 a = 0, b = 0;
#pragma unroll
            for (int q = 0; q < 12; q++) {
                ulonglong2 v = wv[q];
                fma2(a, xr2[2 * q], v.x);
                fma2(b, xr2[2 * q + 1], v.y);
            }
            fma2(a, xr2[24], ((const u64*)w)[24]);
            float2 fa = up2(a), fb = up2(b);
            acc[n] += (fa.x + fa.y) + (fb.x + fb.y);
        }
    }
    float* o = out + (size_t)pos * 45;
#pragma unroll
    for (int n = 0; n < 45; n++) o[n] = acc[n];
}

// ---------------------------------------------------------------------------
extern "C" void kernel_launch(void* const* d_in, const int* in_sizes, int n_in,
                              void* d_out, int out_size) {
    const int*   x       = (const int*)  d_in[0];
    const float* emb_f1  = (const float*)d_in[1];
    const float* emb_b1  = (const float*)d_in[2];
    const float* h0_f1   = (const float*)d_in[3];
    const float* c0_f1   = (const float*)d_in[4];
    const float* Wih_f1  = (const float*)d_in[5];
    const float* Whh_f1  = (const float*)d_in[6];
    const float* bih_f1  = (const float*)d_in[7];
    const float* bhh_f1  = (const float*)d_in[8];
    const float* h0_b1   = (const float*)d_in[9];
    const float* c0_b1   = (const float*)d_in[10];
    const float* Wih_b1  = (const float*)d_in[11];
    const float* Whh_b1  = (const float*)d_in[12];
    const float* bih_b1  = (const float*)d_in[13];
    const float* bhh_b1  = (const float*)d_in[14];
    const float* h0_f2   = (const float*)d_in[15];
    const float* c0_f2   = (const float*)d_in[16];
    const float* Wih_f2  = (const float*)d_in[17];
    const float* Whh_f2  = (const float*)d_in[18];
    const float* bih_f2  = (const float*)d_in[19];
    const float* bhh_f2  = (const float*)d_in[20];
    const float* h0_b2   = (const float*)d_in[21];
    const float* c0_b2   = (const float*)d_in[22];
    const float* Wih_b2  = (const float*)d_in[23];
    const float* Whh_b2  = (const float*)d_in[24];
    const float* bih_b2  = (const float*)d_in[25];
    const float* bhh_b2  = (const float*)d_in[26];
    const float* lin_w   = (const float*)d_in[27];
    const float* lin_b   = (const float*)d_in[28];
    float* out = (float*)d_out;

    int nvocab = in_sizes[1] / 20;
    if (nvocab > 50000) nvocab = 50000;
    int tg_blocks = (nvocab + 255) / 256;

    detect_kernel<<<1, 1>>>(x);
    convert_kernel<<<1024, 256>>>(x);
    tokgate_kernel<<<2 * tg_blocks, 256>>>(emb_f1, Wih_f1, emb_b1, Wih_b1,
                                           tg_blocks, nvocab);
    r1_kernel<<<512, 128>>>(h0_f1, c0_f1, Whh_f1, bih_f1, bhh_f1,
                            h0_b1, c0_b1, Whh_b1, bih_b1, bhh_b1);
    xg2_kernel<<<8192, 256>>>(Wih_f2, Wih_b2);
    r2_kernel<<<342, 224>>>(h0_f2, c0_f2, Whh_f2, bih_f2, bhh_f2,
                            h0_b2, c0_b2, Whh_b2, bih_b2, bhh_b2);
    out_kernel<<<1024, 256>>>(lin_w, lin_b, out);
}